// round 11
// baseline (speedup 1.0000x reference)
#include <cuda_runtime.h>
#include <cuda_bf16.h>
#include <cuda_fp16.h>
#include <cstdint>

#define S_LEN   4096
#define HID     2048
#define NH      16
#define NKV     4
#define DH      128
#define QKV_LD  3072
#define QK16_LD 1280
#define Q_SCALE 0.08838834764831845f
#define CAP     50.0f
// log2-domain softcap constants
#define SC_IN   0.057707801635558534f   // (2/50)*log2(e)
#define SC_C1   72.13475204444817f      // 50*log2(e)
#define SC_C2   144.26950408889634f     // 100*log2(e)

// Scratch (device globals: no cudaMalloc allowed)
__device__ float    g_qkv[(size_t)S_LEN * QKV_LD];
__device__ uint32_t g_qk16[(size_t)S_LEN * QK16_LD];
__device__ uint32_t g_v16[(size_t)S_LEN * 256];
__device__ uint32_t g_hs16[(size_t)S_LEN * 1024];
__device__ uint32_t g_w16[(size_t)3072 * 1024];
__device__ uint32_t g_wo16[(size_t)2048 * 1024];
__device__ uint32_t g_attn16[(size_t)S_LEN * 1024];

// ===========================================================================
// Helpers
// ===========================================================================
__device__ __forceinline__ uint32_t pk(float lo, float hi) {
    uint32_t d;
    asm("cvt.rn.f16x2.f32 %0, %1, %2;" : "=r"(d) : "f"(hi), "f"(lo));
    return d;
}
__device__ __forceinline__ float ex2f(float x) {
    float r;
    asm("ex2.approx.f32 %0, %1;" : "=f"(r) : "f"(x));
    return r;
}
__device__ __forceinline__ float rcpf(float x) {
    float r;
    asm("rcp.approx.f32 %0, %1;" : "=f"(r) : "f"(x));
    return r;
}
__device__ __forceinline__ void mma_f16(float* c, const uint32_t* a, const uint32_t* b) {
    asm volatile(
        "mma.sync.aligned.m16n8k16.row.col.f32.f16.f16.f32 "
        "{%0,%1,%2,%3}, {%4,%5,%6,%7}, {%8,%9}, {%0,%1,%2,%3};"
        : "+f"(c[0]), "+f"(c[1]), "+f"(c[2]), "+f"(c[3])
        : "r"(a[0]), "r"(a[1]), "r"(a[2]), "r"(a[3]), "r"(b[0]), "r"(b[1]));
}
__device__ __forceinline__ uint32_t smem_u32(const void* p) {
    uint32_t a;
    asm("{ .reg .u64 t; cvta.to.shared.u64 t, %1; cvt.u32.u64 %0, t; }"
        : "=r"(a) : "l"(p));
    return a;
}
#define LDSM4(r0, r1, r2, r3, addr) \
    asm volatile("ldmatrix.sync.aligned.m8n8.x4.shared.b16 {%0,%1,%2,%3}, [%4];" \
        : "=r"(r0), "=r"(r1), "=r"(r2), "=r"(r3) : "r"(addr))
#define LDSM4T(r0, r1, r2, r3, addr) \
    asm volatile("ldmatrix.sync.aligned.m8n8.x4.trans.shared.b16 {%0,%1,%2,%3}, [%4];" \
        : "=r"(r0), "=r"(r1), "=r"(r2), "=r"(r3) : "r"(addr))
#define CP_A16(saddr, gptr) \
    asm volatile("cp.async.cg.shared.global [%0], [%1], 16;" :: "r"(saddr), "l"(gptr))
#define CP_COMMIT() asm volatile("cp.async.commit_group;" ::: "memory")
#define CP_WAIT(n)  asm volatile("cp.async.wait_group %0;" :: "n"(n) : "memory")

// ---------------------------------------------------------------------------
// Fused f32 -> fp16x2 convert (one launch)
// ---------------------------------------------------------------------------
#define N_HS 2097152
#define N_WQ 1048576
#define N_WK 262144
#define N_WV 262144
#define N_WO 1048576
#define N_CVT (N_HS + N_WQ + N_WK + N_WV + N_WO)

__global__ void cvt_all(const float* __restrict__ hs, const float* __restrict__ wq,
                        const float* __restrict__ wk, const float* __restrict__ wv,
                        const float* __restrict__ wo,
                        uint32_t* __restrict__ hs16, uint32_t* __restrict__ w16,
                        uint32_t* __restrict__ wo16)
{
    int i = blockIdx.x * 256 + threadIdx.x;
    if (i >= N_CVT) return;
    const float* src; uint32_t* dst; int j = i;
    if (j < N_HS)                 { src = hs; dst = hs16; }
    else if ((j -= N_HS) < N_WQ)  { src = wq; dst = w16; }
    else if ((j -= N_WQ) < N_WK)  { src = wk; dst = w16 + (size_t)2048 * 1024; }
    else if ((j -= N_WK) < N_WV)  { src = wv; dst = w16 + (size_t)2560 * 1024; }
    else { j -= N_WV;               src = wo; dst = wo16; }
    float4 v = ((const float4*)src)[j];
    ((uint2*)dst)[j] = make_uint2(pk(v.x, v.y), pk(v.z, v.w));
}

// ===========================================================================
// FP16 GEMM (unchanged)
// ===========================================================================
#define KC 64
#define STAGES 3
#define AST 16384
#define BST 16384
#define STG (AST + BST)
#define GEMM_SMEM (STAGES * STG)

__global__ __launch_bounds__(256, 2) void gemm_h(
    const __half* __restrict__ A, const __half* __restrict__ B,
    float* __restrict__ C, int Kd, int ldc)
{
    extern __shared__ __align__(128) char smc[];
    const uint32_t sb = smem_u32(smc);

    const int tid  = threadIdx.x;
    const int lane = tid & 31;
    const int warp = tid >> 5;
    const int wm   = warp >> 1;
    const int wn   = warp & 1;
    const int bm   = blockIdx.y * 128;
    const int bnG  = blockIdx.x * 128;
    const int NC   = Kd / KC;

    const int lrow = tid >> 3;
    const int lc16 = tid & 7;
    const __half* Ag = A + (size_t)(bm + lrow) * Kd + lc16 * 8;
    const __half* Bg = B + (size_t)(bnG + lrow) * Kd + lc16 * 8;

    uint32_t so[4];
#pragma unroll
    for (int it = 0; it < 4; it++) {
        int row = lrow + it * 32;
        so[it] = (uint32_t)(row * 128 + ((lc16 ^ (row & 7)) << 4));
    }

    const int l15 = lane & 15;
    const int lh  = lane >> 4;
    int aRow[2], bRow[4];
#pragma unroll
    for (int mi = 0; mi < 2; mi++) aRow[mi] = wm * 32 + mi * 16 + l15;
#pragma unroll
    for (int nt = 0; nt < 4; nt++) bRow[nt] = wn * 64 + nt * 16 + l15;

    float acc[2][8][4];
#pragma unroll
    for (int i = 0; i < 2; i++)
#pragma unroll
        for (int j = 0; j < 8; j++)
#pragma unroll
            for (int e = 0; e < 4; e++) acc[i][j][e] = 0.f;

#pragma unroll
    for (int s = 0; s < STAGES - 1; s++) {
        const uint32_t sA = sb + s * STG;
        const uint32_t sB = sA + AST;
        const size_t ko = (size_t)s * KC;
#pragma unroll
        for (int it = 0; it < 4; it++) {
            CP_A16(sA + so[it], Ag + (size_t)(it * 32) * Kd + ko);
            CP_A16(sB + so[it], Bg + (size_t)(it * 32) * Kd + ko);
        }
        CP_COMMIT();
    }

    for (int ic = 0; ic < NC; ic++) {
        if (ic + STAGES - 1 < NC) {
            const int s = (ic + STAGES - 1) % STAGES;
            const uint32_t sA = sb + s * STG;
            const uint32_t sB = sA + AST;
            const size_t ko = (size_t)(ic + STAGES - 1) * KC;
#pragma unroll
            for (int it = 0; it < 4; it++) {
                CP_A16(sA + so[it], Ag + (size_t)(it * 32) * Kd + ko);
                CP_A16(sB + so[it], Bg + (size_t)(it * 32) * Kd + ko);
            }
        }
        CP_COMMIT();
        CP_WAIT(STAGES - 1);
        __syncthreads();

        const uint32_t sA = sb + (ic % STAGES) * STG;
        const uint32_t sB = sA + AST;

#pragma unroll
        for (int ki = 0; ki < 4; ki++) {
            const int kb = ki * 2 + lh;
            uint32_t af[2][4], bv[4][4];
#pragma unroll
            for (int mi = 0; mi < 2; mi++) {
                uint32_t ad = sA + aRow[mi] * 128 + (((kb ^ (aRow[mi] & 7))) << 4);
                LDSM4(af[mi][0], af[mi][1], af[mi][2], af[mi][3], ad);
            }
#pragma unroll
            for (int nt = 0; nt < 4; nt++) {
                uint32_t bd = sB + bRow[nt] * 128 + (((kb ^ (bRow[nt] & 7))) << 4);
                LDSM4(bv[nt][0], bv[nt][1], bv[nt][2], bv[nt][3], bd);
            }
#pragma unroll
            for (int mi = 0; mi < 2; mi++)
#pragma unroll
                for (int j = 0; j < 8; j++) {
                    uint32_t bf[2] = { bv[j >> 1][(j & 1)], bv[j >> 1][2 + (j & 1)] };
                    mma_f16(acc[mi][j], af[mi], bf);
                }
        }
        __syncthreads();
    }

    const int g = lane >> 2, t = lane & 3;
#pragma unroll
    for (int mi = 0; mi < 2; mi++)
#pragma unroll
        for (int j = 0; j < 8; j++) {
            const int row = bm + wm * 32 + mi * 16 + g;
            const int col = bnG + wn * 64 + j * 8 + t * 2;
            float* p0 = C + (size_t)row * ldc + col;
            float* p1 = C + (size_t)(row + 8) * ldc + col;
            *(float2*)p0 = make_float2(acc[mi][j][0], acc[mi][j][1]);
            *(float2*)p1 = make_float2(acc[mi][j][2], acc[mi][j][3]);
        }
}

// ---------------------------------------------------------------------------
// RoPE + Q scale -> g_qk16; V -> g_v16
// ---------------------------------------------------------------------------
__global__ void rope_pack(const float* __restrict__ qkv,
                          uint32_t* __restrict__ qk16, uint32_t* __restrict__ v16,
                          const float* __restrict__ cosp, const float* __restrict__ sinp)
{
    const int s = blockIdx.x;
    const float* c  = cosp + (size_t)s * DH;
    const float* sn = sinp + (size_t)s * DH;
    const float* row = qkv + (size_t)s * QKV_LD;
    uint32_t* orow = qk16 + (size_t)s * QK16_LD;
    uint32_t* vrow = v16 + (size_t)s * 256;
    for (int i = threadIdx.x; i < 24 * 32; i += blockDim.x) {
        int hh = i >> 5;
        int c0 = i & 31;
        if (hh < 20) {
            int d0 = 2 * c0;
            int base = (hh < 16) ? hh * 128 : (2048 + (hh - 16) * 128);
            float x1a = row[base + d0],      x1b = row[base + d0 + 1];
            float x2a = row[base + d0 + 64], x2b = row[base + d0 + 65];
            float y1a = x1a * c[d0]      - x2a * sn[d0];
            float y1b = x1b * c[d0 + 1]  - x2b * sn[d0 + 1];
            float y2a = x2a * c[d0 + 64] + x1a * sn[d0 + 64];
            float y2b = x2b * c[d0 + 65] + x1b * sn[d0 + 65];
            if (hh < 16) { y1a *= Q_SCALE; y1b *= Q_SCALE; y2a *= Q_SCALE; y2b *= Q_SCALE; }
            int obase = (hh < 16) ? hh * 64 : (1024 + (hh - 16) * 64);
            orow[obase + c0]      = pk(y1a, y1b);
            orow[obase + 32 + c0] = pk(y2a, y2b);
        } else {
            int base = 2560 + (hh - 20) * 128;
            int obase = (hh - 20) * 64;
            vrow[obase + c0]      = pk(row[base + 2 * c0],      row[base + 2 * c0 + 1]);
            vrow[obase + 32 + c0] = pk(row[base + 64 + 2 * c0], row[base + 64 + 2 * c0 + 1]);
        }
    }
}

// ===========================================================================
// Flash attention: register-resident P (C-frag == A-frag identity),
// branch-split causal mask, log2 softmax, ones-MMA row sums. 2 CTAs/SM.
// smem: Q 32K | K0/K1 32K | V0/V1 32K = 96 KB
// ===========================================================================
#define ATTN_SMEM 98304
#define SQ_OFF 0
#define SK_OFF 32768
#define SV_OFF 65536

__global__ __launch_bounds__(256, 2) void attn_mma(
    const uint32_t* __restrict__ qk16, const uint32_t* __restrict__ v16,
    uint32_t* __restrict__ out16)
{
    extern __shared__ __align__(128) char sm[];
    const uint32_t sb = smem_u32(sm);
    const uint32_t sQ = sb + SQ_OFF;

    const int tid  = threadIdx.x;
    const int lane = tid & 31;
    const int warp = tid >> 5;
    const int qb   = (int)gridDim.x - 1 - (int)blockIdx.x;
    const int h    = blockIdx.y;
    const int kvg  = h >> 2;

    const int g = lane >> 2, t = lane & 3;
    const int l15 = lane & 15, lh = lane >> 4;
    const int e7 = l15 & 7;

    const char* Qg = (const char*)(qk16 + (size_t)h * 64);
    const char* Kg = (const char*)(qk16 + 1024 + (size_t)kvg * 64);
    const char* Vg = (const char*)(v16 + (size_t)kvg * 64);

#pragma unroll
    for (int i = 0; i < 8; i++) {
        int idx = tid + i * 256;
        int row = idx >> 4, u = idx & 15;
        CP_A16(sQ + row * 256 + ((u ^ (row & 7)) << 4),
               Qg + (size_t)(qb * 128 + row) * 5120 + u * 16);
    }
#pragma unroll
    for (int i = 0; i < 4; i++) {
        int idx = tid + i * 256;
        int row = idx >> 4, u = idx & 15;
        uint32_t so = row * 256 + ((u ^ (row & 7)) << 4);
        CP_A16(sb + SK_OFF + so, Kg + (size_t)row * 5120 + u * 16);
        CP_A16(sb + SV_OFF + so, Vg + (size_t)row * 1024 + u * 16);
    }
    CP_COMMIT();

    float oacc[16][4], lacc[4];
#pragma unroll
    for (int i = 0; i < 16; i++)
#pragma unroll
        for (int e = 0; e < 4; e++) oacc[i][e] = 0.f;
#pragma unroll
    for (int e = 0; e < 4; e++) lacc[e] = 0.f;
    float m0 = -1e30f, m1 = -1e30f;

    const int qr0 = qb * 128 + warp * 16 + g;
    const int ntiles = 2 * qb + 2;

    const uint32_t qbase = sQ + (warp * 16 + l15) * 256;
    const uint32_t kofsL = (uint32_t)(l15 * 256);
    const uint32_t ones2[2] = { 0x3C003C00u, 0x3C003C00u };

    for (int kt = 0; kt < ntiles; kt++) {
        CP_WAIT(0);
        __syncthreads();

        if (kt + 1 < ntiles) {
            const uint32_t dK = sb + SK_OFF + ((kt + 1) & 1) * 16384;
            const uint32_t dV = sb + SV_OFF + ((kt + 1) & 1) * 16384;
#pragma unroll
            for (int i = 0; i < 4; i++) {
                int idx = tid + i * 256;
                int row = idx >> 4, u = idx & 15;
                uint32_t so = row * 256 + ((u ^ (row & 7)) << 4);
                CP_A16(dK + so, Kg + (size_t)((kt + 1) * 64 + row) * 5120 + u * 16);
                CP_A16(dV + so, Vg + (size_t)((kt + 1) * 64 + row) * 1024 + u * 16);
            }
            CP_COMMIT();
        }

        const uint32_t cK = sb + SK_OFF + (kt & 1) * 16384;
        const uint32_t cV = sb + SV_OFF + (kt & 1) * 16384;

        // ---- QK ----
        float acc[8][4];
#pragma unroll
        for (int nt = 0; nt < 8; nt++)
#pragma unroll
            for (int e = 0; e < 4; e++) acc[nt][e] = 0.f;

#pragma unroll
        for (int ki = 0; ki < 8; ki++) {
            const uint32_t xo = (uint32_t)(((ki * 2 + lh) ^ e7) << 4);
            uint32_t af[4];
            LDSM4(af[0], af[1], af[2], af[3], qbase + xo);
            const uint32_t kb0 = cK + kofsL + xo;
#pragma unroll
            for (int ntp = 0; ntp < 4; ntp++) {
                uint32_t r0, r1, r2, r3;
                LDSM4(r0, r1, r2, r3, kb0 + ntp * 4096);
                uint32_t bf0[2] = { r0, r2 };
                uint32_t bf1[2] = { r1, r3 };
                mma_f16(acc[2 * ntp],     af, bf0);
                mma_f16(acc[2 * ntp + 1], af, bf1);
            }
        }

        // ---- softcap + row max (branch-split causal mask) ----
        float mt0 = -1e30f, mt1 = -1e30f;
        if (kt >= 2 * qb) {
            const int kb = kt * 64 + 2 * t;
            const int qrA = qr0, qrB = qr0 + 8;
#pragma unroll
            for (int nt = 0; nt < 8; nt++) {
#pragma unroll
                for (int e = 0; e < 4; e++) {
                    float w = ex2f(acc[nt][e] * SC_IN);
                    float v = fmaf(-SC_C2, rcpf(w + 1.f), SC_C1);
                    int kc = kb + nt * 8 + (e & 1);
                    if (kc > ((e >> 1) ? qrB : qrA)) v = -1e30f;
                    acc[nt][e] = v;
                    if (e < 2) mt0 = fmaxf(mt0, v); else mt1 = fmaxf(mt1, v);
                }
            }
        } else {
#pragma unroll
            for (int nt = 0; nt < 8; nt++) {
#pragma unroll
                for (int e = 0; e < 4; e++) {
                    float w = ex2f(acc[nt][e] * SC_IN);
                    float v = fmaf(-SC_C2, rcpf(w + 1.f), SC_C1);
                    acc[nt][e] = v;
                    if (e < 2) mt0 = fmaxf(mt0, v); else mt1 = fmaxf(mt1, v);
                }
            }
        }
        mt0 = fmaxf(mt0, __shfl_xor_sync(0xffffffffu, mt0, 1));
        mt0 = fmaxf(mt0, __shfl_xor_sync(0xffffffffu, mt0, 2));
        mt1 = fmaxf(mt1, __shfl_xor_sync(0xffffffffu, mt1, 1));
        mt1 = fmaxf(mt1, __shfl_xor_sync(0xffffffffu, mt1, 2));

        const bool nochg = (mt0 <= m0) && (mt1 <= m1);
        if (!__all_sync(0xffffffffu, nochg)) {
            const float mn0 = fmaxf(m0, mt0), mn1 = fmaxf(m1, mt1);
            const float al0 = ex2f(m0 - mn0), al1 = ex2f(m1 - mn1);
            m0 = mn0; m1 = mn1;
#pragma unroll
            for (int ni = 0; ni < 16; ni++) {
                oacc[ni][0] *= al0; oacc[ni][1] *= al0;
                oacc[ni][2] *= al1; oacc[ni][3] *= al1;
            }
            lacc[0] *= al0; lacc[1] *= al0;
            lacc[2] *= al1; lacc[3] *= al1;
        }

        // ---- PV: P built directly from C-fragments (no smem round-trip) ----
#pragma unroll
        for (int ki = 0; ki < 4; ki++) {
            uint32_t af[4];
            {
                const int n0 = 2 * ki, n1 = 2 * ki + 1;
                float p00 = ex2f(acc[n0][0] - m0), p01 = ex2f(acc[n0][1] - m0);
                float p02 = ex2f(acc[n0][2] - m1), p03 = ex2f(acc[n0][3] - m1);
                float p10 = ex2f(acc[n1][0] - m0), p11 = ex2f(acc[n1][1] - m0);
                float p12 = ex2f(acc[n1][2] - m1), p13 = ex2f(acc[n1][3] - m1);
                af[0] = pk(p00, p01);
                af[1] = pk(p02, p03);
                af[2] = pk(p10, p11);
                af[3] = pk(p12, p13);
            }
            mma_f16(lacc, af, ones2);
            const uint32_t vb0 = cV + ki * 4096 + kofsL;
#pragma unroll
            for (int nip = 0; nip < 8; nip++) {
                uint32_t r0, r1, r2, r3;
                uint32_t va = vb0 + ((uint32_t)((nip * 2 + lh) ^ e7) << 4);
                LDSM4T(r0, r1, r2, r3, va);
                uint32_t bf0[2] = { r0, r1 };
                uint32_t bf1[2] = { r2, r3 };
                mma_f16(oacc[2 * nip],     af, bf0);
                mma_f16(oacc[2 * nip + 1], af, bf1);
            }
        }
    }

    // ---- epilogue: fp16 output, l from lacc ----
    const float inv0 = __fdividef(1.f, lacc[0]);
    const float inv1 = __fdividef(1.f, lacc[2]);
    uint32_t* o0 = out16 + (size_t)qr0 * 1024 + h * 64 + t;
    uint32_t* o1 = out16 + (size_t)(qr0 + 8) * 1024 + h * 64 + t;
#pragma unroll
    for (int ni = 0; ni < 16; ni++) {
        o0[ni * 4] = pk(oacc[ni][0] * inv0, oacc[ni][1] * inv0);
        o1[ni * 4] = pk(oacc[ni][2] * inv1, oacc[ni][3] * inv1);
    }
}

// ---------------------------------------------------------------------------
// Inputs (metadata order): hidden_states, cos, sin, attention_mask, wq, wk, wv, wo
// ---------------------------------------------------------------------------
extern "C" void kernel_launch(void* const* d_in, const int* in_sizes, int n_in,
                              void* d_out, int out_size)
{
    const float* hs   = (const float*)d_in[0];
    const float* cosp = (const float*)d_in[1];
    const float* sinp = (const float*)d_in[2];
    const float* wq   = (const float*)d_in[4];
    const float* wk   = (const float*)d_in[5];
    const float* wv   = (const float*)d_in[6];
    const float* wo   = (const float*)d_in[7];
    float* out = (float*)d_out;

    float* qkv = nullptr; uint32_t* qk16 = nullptr; uint32_t* v16 = nullptr;
    uint32_t* hs16 = nullptr; uint32_t* w16 = nullptr;
    uint32_t* wo16 = nullptr; uint32_t* attn16 = nullptr;
    cudaGetSymbolAddress((void**)&qkv,    g_qkv);
    cudaGetSymbolAddress((void**)&qk16,   g_qk16);
    cudaGetSymbolAddress((void**)&v16,    g_v16);
    cudaGetSymbolAddress((void**)&hs16,   g_hs16);
    cudaGetSymbolAddress((void**)&w16,    g_w16);
    cudaGetSymbolAddress((void**)&wo16,   g_wo16);
    cudaGetSymbolAddress((void**)&attn16, g_attn16);

    cudaFuncSetAttribute(gemm_h, cudaFuncAttributeMaxDynamicSharedMemorySize, GEMM_SMEM);
    cudaFuncSetAttribute(attn_mma, cudaFuncAttributeMaxDynamicSharedMemorySize, ATTN_SMEM);

    dim3 blk(256);
    cvt_all<<<(N_CVT + 255) / 256, blk>>>(hs, wq, wk, wv, wo, hs16, w16, wo16);
    gemm_h<<<dim3(3072 / 128, S_LEN / 128), blk, GEMM_SMEM>>>(
        (const __half*)hs16, (const __half*)w16, qkv, HID, QKV_LD);
    rope_pack<<<S_LEN, 256>>>(qkv, qk16, v16, cosp, sinp);
    attn_mma<<<dim3(S_LEN / 128, NH), blk, ATTN_SMEM>>>(qk16, v16, attn16);
    gemm_h<<<dim3(2048 / 128, S_LEN / 128), blk, GEMM_SMEM>>>(
        (const __half*)attn16, (const __half*)wo16, out, HID, HID);
}

// round 12
// speedup vs baseline: 1.4411x; 1.4411x over previous
#include <cuda_runtime.h>
#include <cuda_bf16.h>
#include <cuda_fp16.h>
#include <cstdint>

#define S_LEN   4096
#define HID     2048
#define NH      16
#define NKV     4
#define DH      128
#define QKV_LD  3072
#define QK16_LD 1280
#define Q_SCALE 0.08838834764831845f
#define CAP     50.0f
// log2-domain softcap constants
#define SC_IN   0.057707801635558534f   // (2/50)*log2(e)
#define SC_C1   72.13475204444817f      // 50*log2(e)
#define SC_C2   144.26950408889634f     // 100*log2(e)

// Scratch (device globals: no cudaMalloc allowed)
__device__ float    g_qkv[(size_t)S_LEN * QKV_LD];
__device__ uint32_t g_qk16[(size_t)S_LEN * QK16_LD];
__device__ uint32_t g_v16[(size_t)S_LEN * 256];
__device__ uint32_t g_hs16[(size_t)S_LEN * 1024];
__device__ uint32_t g_w16[(size_t)3072 * 1024];
__device__ uint32_t g_wo16[(size_t)2048 * 1024];
__device__ uint32_t g_attn16[(size_t)S_LEN * 1024];

// ===========================================================================
// Helpers
// ===========================================================================
__device__ __forceinline__ uint32_t pk(float lo, float hi) {
    uint32_t d;
    asm("cvt.rn.f16x2.f32 %0, %1, %2;" : "=r"(d) : "f"(hi), "f"(lo));
    return d;
}
__device__ __forceinline__ float ex2f(float x) {
    float r;
    asm("ex2.approx.f32 %0, %1;" : "=f"(r) : "f"(x));
    return r;
}
__device__ __forceinline__ float rcpf(float x) {
    float r;
    asm("rcp.approx.f32 %0, %1;" : "=f"(r) : "f"(x));
    return r;
}
__device__ __forceinline__ void mma_f16(float* c, const uint32_t* a, const uint32_t* b) {
    asm volatile(
        "mma.sync.aligned.m16n8k16.row.col.f32.f16.f16.f32 "
        "{%0,%1,%2,%3}, {%4,%5,%6,%7}, {%8,%9}, {%0,%1,%2,%3};"
        : "+f"(c[0]), "+f"(c[1]), "+f"(c[2]), "+f"(c[3])
        : "r"(a[0]), "r"(a[1]), "r"(a[2]), "r"(a[3]), "r"(b[0]), "r"(b[1]));
}
__device__ __forceinline__ uint32_t smem_u32(const void* p) {
    uint32_t a;
    asm("{ .reg .u64 t; cvta.to.shared.u64 t, %1; cvt.u32.u64 %0, t; }"
        : "=r"(a) : "l"(p));
    return a;
}
#define LDSM4(r0, r1, r2, r3, addr) \
    asm volatile("ldmatrix.sync.aligned.m8n8.x4.shared.b16 {%0,%1,%2,%3}, [%4];" \
        : "=r"(r0), "=r"(r1), "=r"(r2), "=r"(r3) : "r"(addr))
#define LDSM4T(r0, r1, r2, r3, addr) \
    asm volatile("ldmatrix.sync.aligned.m8n8.x4.trans.shared.b16 {%0,%1,%2,%3}, [%4];" \
        : "=r"(r0), "=r"(r1), "=r"(r2), "=r"(r3) : "r"(addr))
#define CP_A16(saddr, gptr) \
    asm volatile("cp.async.cg.shared.global [%0], [%1], 16;" :: "r"(saddr), "l"(gptr))
#define CP_COMMIT() asm volatile("cp.async.commit_group;" ::: "memory")
#define CP_WAIT(n)  asm volatile("cp.async.wait_group %0;" :: "n"(n) : "memory")

// ---------------------------------------------------------------------------
// Fused f32 -> fp16x2 convert (one launch)
// ---------------------------------------------------------------------------
#define N_HS 2097152
#define N_WQ 1048576
#define N_WK 262144
#define N_WV 262144
#define N_WO 1048576
#define N_CVT (N_HS + N_WQ + N_WK + N_WV + N_WO)

__global__ void cvt_all(const float* __restrict__ hs, const float* __restrict__ wq,
                        const float* __restrict__ wk, const float* __restrict__ wv,
                        const float* __restrict__ wo,
                        uint32_t* __restrict__ hs16, uint32_t* __restrict__ w16,
                        uint32_t* __restrict__ wo16)
{
    int i = blockIdx.x * 256 + threadIdx.x;
    if (i >= N_CVT) return;
    const float* src; uint32_t* dst; int j = i;
    if (j < N_HS)                 { src = hs; dst = hs16; }
    else if ((j -= N_HS) < N_WQ)  { src = wq; dst = w16; }
    else if ((j -= N_WQ) < N_WK)  { src = wk; dst = w16 + (size_t)2048 * 1024; }
    else if ((j -= N_WK) < N_WV)  { src = wv; dst = w16 + (size_t)2560 * 1024; }
    else { j -= N_WV;               src = wo; dst = wo16; }
    float4 v = ((const float4*)src)[j];
    ((uint2*)dst)[j] = make_uint2(pk(v.x, v.y), pk(v.z, v.w));
}

// ===========================================================================
// FP16 GEMM (unchanged)
// ===========================================================================
#define KC 64
#define STAGES 3
#define AST 16384
#define BST 16384
#define STG (AST + BST)
#define GEMM_SMEM (STAGES * STG)

__global__ __launch_bounds__(256, 2) void gemm_h(
    const __half* __restrict__ A, const __half* __restrict__ B,
    float* __restrict__ C, int Kd, int ldc)
{
    extern __shared__ __align__(128) char smc[];
    const uint32_t sb = smem_u32(smc);

    const int tid  = threadIdx.x;
    const int lane = tid & 31;
    const int warp = tid >> 5;
    const int wm   = warp >> 1;
    const int wn   = warp & 1;
    const int bm   = blockIdx.y * 128;
    const int bnG  = blockIdx.x * 128;
    const int NC   = Kd / KC;

    const int lrow = tid >> 3;
    const int lc16 = tid & 7;
    const __half* Ag = A + (size_t)(bm + lrow) * Kd + lc16 * 8;
    const __half* Bg = B + (size_t)(bnG + lrow) * Kd + lc16 * 8;

    uint32_t so[4];
#pragma unroll
    for (int it = 0; it < 4; it++) {
        int row = lrow + it * 32;
        so[it] = (uint32_t)(row * 128 + ((lc16 ^ (row & 7)) << 4));
    }

    const int l15 = lane & 15;
    const int lh  = lane >> 4;
    int aRow[2], bRow[4];
#pragma unroll
    for (int mi = 0; mi < 2; mi++) aRow[mi] = wm * 32 + mi * 16 + l15;
#pragma unroll
    for (int nt = 0; nt < 4; nt++) bRow[nt] = wn * 64 + nt * 16 + l15;

    float acc[2][8][4];
#pragma unroll
    for (int i = 0; i < 2; i++)
#pragma unroll
        for (int j = 0; j < 8; j++)
#pragma unroll
            for (int e = 0; e < 4; e++) acc[i][j][e] = 0.f;

#pragma unroll
    for (int s = 0; s < STAGES - 1; s++) {
        const uint32_t sA = sb + s * STG;
        const uint32_t sB = sA + AST;
        const size_t ko = (size_t)s * KC;
#pragma unroll
        for (int it = 0; it < 4; it++) {
            CP_A16(sA + so[it], Ag + (size_t)(it * 32) * Kd + ko);
            CP_A16(sB + so[it], Bg + (size_t)(it * 32) * Kd + ko);
        }
        CP_COMMIT();
    }

    for (int ic = 0; ic < NC; ic++) {
        if (ic + STAGES - 1 < NC) {
            const int s = (ic + STAGES - 1) % STAGES;
            const uint32_t sA = sb + s * STG;
            const uint32_t sB = sA + AST;
            const size_t ko = (size_t)(ic + STAGES - 1) * KC;
#pragma unroll
            for (int it = 0; it < 4; it++) {
                CP_A16(sA + so[it], Ag + (size_t)(it * 32) * Kd + ko);
                CP_A16(sB + so[it], Bg + (size_t)(it * 32) * Kd + ko);
            }
        }
        CP_COMMIT();
        CP_WAIT(STAGES - 1);
        __syncthreads();

        const uint32_t sA = sb + (ic % STAGES) * STG;
        const uint32_t sB = sA + AST;

#pragma unroll
        for (int ki = 0; ki < 4; ki++) {
            const int kb = ki * 2 + lh;
            uint32_t af[2][4], bv[4][4];
#pragma unroll
            for (int mi = 0; mi < 2; mi++) {
                uint32_t ad = sA + aRow[mi] * 128 + (((kb ^ (aRow[mi] & 7))) << 4);
                LDSM4(af[mi][0], af[mi][1], af[mi][2], af[mi][3], ad);
            }
#pragma unroll
            for (int nt = 0; nt < 4; nt++) {
                uint32_t bd = sB + bRow[nt] * 128 + (((kb ^ (bRow[nt] & 7))) << 4);
                LDSM4(bv[nt][0], bv[nt][1], bv[nt][2], bv[nt][3], bd);
            }
#pragma unroll
            for (int mi = 0; mi < 2; mi++)
#pragma unroll
                for (int j = 0; j < 8; j++) {
                    uint32_t bf[2] = { bv[j >> 1][(j & 1)], bv[j >> 1][2 + (j & 1)] };
                    mma_f16(acc[mi][j], af[mi], bf);
                }
        }
        __syncthreads();
    }

    const int g = lane >> 2, t = lane & 3;
#pragma unroll
    for (int mi = 0; mi < 2; mi++)
#pragma unroll
        for (int j = 0; j < 8; j++) {
            const int row = bm + wm * 32 + mi * 16 + g;
            const int col = bnG + wn * 64 + j * 8 + t * 2;
            float* p0 = C + (size_t)row * ldc + col;
            float* p1 = C + (size_t)(row + 8) * ldc + col;
            *(float2*)p0 = make_float2(acc[mi][j][0], acc[mi][j][1]);
            *(float2*)p1 = make_float2(acc[mi][j][2], acc[mi][j][3]);
        }
}

// ---------------------------------------------------------------------------
// RoPE + Q scale -> g_qk16; V -> g_v16
// ---------------------------------------------------------------------------
__global__ void rope_pack(const float* __restrict__ qkv,
                          uint32_t* __restrict__ qk16, uint32_t* __restrict__ v16,
                          const float* __restrict__ cosp, const float* __restrict__ sinp)
{
    const int s = blockIdx.x;
    const float* c  = cosp + (size_t)s * DH;
    const float* sn = sinp + (size_t)s * DH;
    const float* row = qkv + (size_t)s * QKV_LD;
    uint32_t* orow = qk16 + (size_t)s * QK16_LD;
    uint32_t* vrow = v16 + (size_t)s * 256;
    for (int i = threadIdx.x; i < 24 * 32; i += blockDim.x) {
        int hh = i >> 5;
        int c0 = i & 31;
        if (hh < 20) {
            int d0 = 2 * c0;
            int base = (hh < 16) ? hh * 128 : (2048 + (hh - 16) * 128);
            float x1a = row[base + d0],      x1b = row[base + d0 + 1];
            float x2a = row[base + d0 + 64], x2b = row[base + d0 + 65];
            float y1a = x1a * c[d0]      - x2a * sn[d0];
            float y1b = x1b * c[d0 + 1]  - x2b * sn[d0 + 1];
            float y2a = x2a * c[d0 + 64] + x1a * sn[d0 + 64];
            float y2b = x2b * c[d0 + 65] + x1b * sn[d0 + 65];
            if (hh < 16) { y1a *= Q_SCALE; y1b *= Q_SCALE; y2a *= Q_SCALE; y2b *= Q_SCALE; }
            int obase = (hh < 16) ? hh * 64 : (1024 + (hh - 16) * 64);
            orow[obase + c0]      = pk(y1a, y1b);
            orow[obase + 32 + c0] = pk(y2a, y2b);
        } else {
            int base = 2560 + (hh - 20) * 128;
            int obase = (hh - 20) * 64;
            vrow[obase + c0]      = pk(row[base + 2 * c0],      row[base + 2 * c0 + 1]);
            vrow[obase + 32 + c0] = pk(row[base + 64 + 2 * c0], row[base + 64 + 2 * c0 + 1]);
        }
    }
}

// ===========================================================================
// Flash attention: Round-10 structure (P through smem — load-bearing for ILP)
// + branch-split causal mask. 2 CTAs/SM.
// ===========================================================================
#define ATTN_SMEM 114688
#define SQ_OFF 0
#define SK_OFF 32768
#define SV_OFF 65536
#define SP_OFF 98304

__global__ __launch_bounds__(256, 2) void attn_mma(
    const uint32_t* __restrict__ qk16, const uint32_t* __restrict__ v16,
    uint32_t* __restrict__ out16)
{
    extern __shared__ __align__(128) char sm[];
    const uint32_t sb = smem_u32(sm);
    const uint32_t sQ = sb + SQ_OFF;

    const int tid  = threadIdx.x;
    const int lane = tid & 31;
    const int warp = tid >> 5;
    const int qb   = (int)gridDim.x - 1 - (int)blockIdx.x;
    const int h    = blockIdx.y;
    const int kvg  = h >> 2;

    const int g = lane >> 2, t = lane & 3;
    const int l15 = lane & 15, lh = lane >> 4;
    const int e7 = l15 & 7;

    const char* Qg = (const char*)(qk16 + (size_t)h * 64);
    const char* Kg = (const char*)(qk16 + 1024 + (size_t)kvg * 64);
    const char* Vg = (const char*)(v16 + (size_t)kvg * 64);

#pragma unroll
    for (int i = 0; i < 8; i++) {
        int idx = tid + i * 256;
        int row = idx >> 4, u = idx & 15;
        CP_A16(sQ + row * 256 + ((u ^ (row & 7)) << 4),
               Qg + (size_t)(qb * 128 + row) * 5120 + u * 16);
    }
#pragma unroll
    for (int i = 0; i < 4; i++) {
        int idx = tid + i * 256;
        int row = idx >> 4, u = idx & 15;
        uint32_t so = row * 256 + ((u ^ (row & 7)) << 4);
        CP_A16(sb + SK_OFF + so, Kg + (size_t)row * 5120 + u * 16);
        CP_A16(sb + SV_OFF + so, Vg + (size_t)row * 1024 + u * 16);
    }
    CP_COMMIT();

    float oacc[16][4], lacc[4];
#pragma unroll
    for (int i = 0; i < 16; i++)
#pragma unroll
        for (int e = 0; e < 4; e++) oacc[i][e] = 0.f;
#pragma unroll
    for (int e = 0; e < 4; e++) lacc[e] = 0.f;
    float m0 = -1e30f, m1 = -1e30f;

    const int qr0 = qb * 128 + warp * 16 + g;
    const int ntiles = 2 * qb + 2;

    // hoisted bases (kt-invariant)
    const uint32_t qbase = sQ + (warp * 16 + l15) * 256;
    const uint32_t kofsL = (uint32_t)(l15 * 256);
    const uint32_t prd_b = sb + SP_OFF + warp * 2048 + l15 * 128;
    const uint32_t ones2[2] = { 0x3C003C00u, 0x3C003C00u };

    // P store addresses (kt-invariant): 8 nt slots
    uint32_t pst[8];
#pragma unroll
    for (int nt = 0; nt < 8; nt++)
        pst[nt] = (uint32_t)(SP_OFF + warp * 2048 + g * 128 + ((nt ^ (g & 7)) << 4) + t * 4);

    for (int kt = 0; kt < ntiles; kt++) {
        CP_WAIT(0);
        __syncthreads();

        if (kt + 1 < ntiles) {
            const uint32_t dK = sb + SK_OFF + ((kt + 1) & 1) * 16384;
            const uint32_t dV = sb + SV_OFF + ((kt + 1) & 1) * 16384;
#pragma unroll
            for (int i = 0; i < 4; i++) {
                int idx = tid + i * 256;
                int row = idx >> 4, u = idx & 15;
                uint32_t so = row * 256 + ((u ^ (row & 7)) << 4);
                CP_A16(dK + so, Kg + (size_t)((kt + 1) * 64 + row) * 5120 + u * 16);
                CP_A16(dV + so, Vg + (size_t)((kt + 1) * 64 + row) * 1024 + u * 16);
            }
            CP_COMMIT();
        }

        const uint32_t cK = sb + SK_OFF + (kt & 1) * 16384;
        const uint32_t cV = sb + SV_OFF + (kt & 1) * 16384;

        // ---- QK ----
        float acc[8][4];
#pragma unroll
        for (int nt = 0; nt < 8; nt++)
#pragma unroll
            for (int e = 0; e < 4; e++) acc[nt][e] = 0.f;

#pragma unroll
        for (int ki = 0; ki < 8; ki++) {
            const uint32_t xo = (uint32_t)(((ki * 2 + lh) ^ e7) << 4);
            uint32_t af[4];
            LDSM4(af[0], af[1], af[2], af[3], qbase + xo);
            const uint32_t kb0 = cK + kofsL + xo;
#pragma unroll
            for (int ntp = 0; ntp < 4; ntp++) {
                uint32_t r0, r1, r2, r3;
                LDSM4(r0, r1, r2, r3, kb0 + ntp * 4096);
                uint32_t bf0[2] = { r0, r2 };
                uint32_t bf1[2] = { r1, r3 };
                mma_f16(acc[2 * ntp],     af, bf0);
                mma_f16(acc[2 * ntp + 1], af, bf1);
            }
        }

        // ---- softcap (log2 domain) + row max, branch-split causal mask ----
        float mt0 = -1e30f, mt1 = -1e30f;
        if (kt >= 2 * qb) {
            const int kb = kt * 64 + 2 * t;
            const int qrA = qr0, qrB = qr0 + 8;
#pragma unroll
            for (int nt = 0; nt < 8; nt++) {
#pragma unroll
                for (int e = 0; e < 4; e++) {
                    float w = ex2f(acc[nt][e] * SC_IN);
                    float v = fmaf(-SC_C2, rcpf(w + 1.f), SC_C1);
                    int kc = kb + nt * 8 + (e & 1);
                    if (kc > ((e >> 1) ? qrB : qrA)) v = -1e30f;
                    acc[nt][e] = v;
                    if (e < 2) mt0 = fmaxf(mt0, v); else mt1 = fmaxf(mt1, v);
                }
            }
        } else {
#pragma unroll
            for (int nt = 0; nt < 8; nt++) {
#pragma unroll
                for (int e = 0; e < 4; e++) {
                    float w = ex2f(acc[nt][e] * SC_IN);
                    float v = fmaf(-SC_C2, rcpf(w + 1.f), SC_C1);
                    acc[nt][e] = v;
                    if (e < 2) mt0 = fmaxf(mt0, v); else mt1 = fmaxf(mt1, v);
                }
            }
        }
        mt0 = fmaxf(mt0, __shfl_xor_sync(0xffffffffu, mt0, 1));
        mt0 = fmaxf(mt0, __shfl_xor_sync(0xffffffffu, mt0, 2));
        mt1 = fmaxf(mt1, __shfl_xor_sync(0xffffffffu, mt1, 1));
        mt1 = fmaxf(mt1, __shfl_xor_sync(0xffffffffu, mt1, 2));

        const bool nochg = (mt0 <= m0) && (mt1 <= m1);
        if (!__all_sync(0xffffffffu, nochg)) {
            const float mn0 = fmaxf(m0, mt0), mn1 = fmaxf(m1, mt1);
            const float al0 = ex2f(m0 - mn0), al1 = ex2f(m1 - mn1);
            m0 = mn0; m1 = mn1;
#pragma unroll
            for (int ni = 0; ni < 16; ni++) {
                oacc[ni][0] *= al0; oacc[ni][1] *= al0;
                oacc[ni][2] *= al1; oacc[ni][3] *= al1;
            }
            lacc[0] *= al0; lacc[1] *= al0;
            lacc[2] *= al1; lacc[3] *= al1;
        }

        // ---- p = ex2(v - m), pack, store to P smem ----
#pragma unroll
        for (int nt = 0; nt < 8; nt++) {
            float p0 = ex2f(acc[nt][0] - m0);
            float p1 = ex2f(acc[nt][1] - m0);
            float p2 = ex2f(acc[nt][2] - m1);
            float p3 = ex2f(acc[nt][3] - m1);
            *(uint32_t*)(sm + pst[nt])             = pk(p0, p1);
            *(uint32_t*)(sm + pst[nt] + 8 * 128)   = pk(p2, p3);
        }
        __syncwarp();

        // ---- PV + ones-MMA row sum ----
#pragma unroll
        for (int ki = 0; ki < 4; ki++) {
            const uint32_t xo = (uint32_t)(((ki * 2 + lh) ^ e7) << 4);
            uint32_t af[4];
            LDSM4(af[0], af[1], af[2], af[3], prd_b + xo);
            mma_f16(lacc, af, ones2);
            const uint32_t vb0 = cV + ki * 4096 + kofsL;
#pragma unroll
            for (int nip = 0; nip < 8; nip++) {
                uint32_t r0, r1, r2, r3;
                uint32_t va = vb0 + ((uint32_t)((nip * 2 + lh) ^ e7) << 4);
                LDSM4T(r0, r1, r2, r3, va);
                uint32_t bf0[2] = { r0, r1 };
                uint32_t bf1[2] = { r2, r3 };
                mma_f16(oacc[2 * nip],     af, bf0);
                mma_f16(oacc[2 * nip + 1], af, bf1);
            }
        }
    }

    // ---- epilogue: fp16 output, l from lacc ----
    const float inv0 = __fdividef(1.f, lacc[0]);
    const float inv1 = __fdividef(1.f, lacc[2]);
    uint32_t* o0 = out16 + (size_t)qr0 * 1024 + h * 64 + t;
    uint32_t* o1 = out16 + (size_t)(qr0 + 8) * 1024 + h * 64 + t;
#pragma unroll
    for (int ni = 0; ni < 16; ni++) {
        o0[ni * 4] = pk(oacc[ni][0] * inv0, oacc[ni][1] * inv0);
        o1[ni * 4] = pk(oacc[ni][2] * inv1, oacc[ni][3] * inv1);
    }
}

// ---------------------------------------------------------------------------
// Inputs (metadata order): hidden_states, cos, sin, attention_mask, wq, wk, wv, wo
// ---------------------------------------------------------------------------
extern "C" void kernel_launch(void* const* d_in, const int* in_sizes, int n_in,
                              void* d_out, int out_size)
{
    const float* hs   = (const float*)d_in[0];
    const float* cosp = (const float*)d_in[1];
    const float* sinp = (const float*)d_in[2];
    const float* wq   = (const float*)d_in[4];
    const float* wk   = (const float*)d_in[5];
    const float* wv   = (const float*)d_in[6];
    const float* wo   = (const float*)d_in[7];
    float* out = (float*)d_out;

    float* qkv = nullptr; uint32_t* qk16 = nullptr; uint32_t* v16 = nullptr;
    uint32_t* hs16 = nullptr; uint32_t* w16 = nullptr;
    uint32_t* wo16 = nullptr; uint32_t* attn16 = nullptr;
    cudaGetSymbolAddress((void**)&qkv,    g_qkv);
    cudaGetSymbolAddress((void**)&qk16,   g_qk16);
    cudaGetSymbolAddress((void**)&v16,    g_v16);
    cudaGetSymbolAddress((void**)&hs16,   g_hs16);
    cudaGetSymbolAddress((void**)&w16,    g_w16);
    cudaGetSymbolAddress((void**)&wo16,   g_wo16);
    cudaGetSymbolAddress((void**)&attn16, g_attn16);

    cudaFuncSetAttribute(gemm_h, cudaFuncAttributeMaxDynamicSharedMemorySize, GEMM_SMEM);
    cudaFuncSetAttribute(attn_mma, cudaFuncAttributeMaxDynamicSharedMemorySize, ATTN_SMEM);

    dim3 blk(256);
    cvt_all<<<(N_CVT + 255) / 256, blk>>>(hs, wq, wk, wv, wo, hs16, w16, wo16);
    gemm_h<<<dim3(3072 / 128, S_LEN / 128), blk, GEMM_SMEM>>>(
        (const __half*)hs16, (const __half*)w16, qkv, HID, QKV_LD);
    rope_pack<<<S_LEN, 256>>>(qkv, qk16, v16, cosp, sinp);
    attn_mma<<<dim3(S_LEN / 128, NH), blk, ATTN_SMEM>>>(qk16, v16, attn16);
    gemm_h<<<dim3(2048 / 128, S_LEN / 128), blk, GEMM_SMEM>>>(
        (const __half*)attn16, (const __half*)wo16, out, HID, HID);
}

// round 13
// speedup vs baseline: 1.4692x; 1.0195x over previous
#include <cuda_runtime.h>
#include <cuda_bf16.h>
#include <cuda_fp16.h>
#include <cstdint>

#define S_LEN   4096
#define HID     2048
#define NH      16
#define NKV     4
#define DH      128
#define QK16_LD 1280
#define Q_SCALE 0.08838834764831845f
#define CAP     50.0f
// log2-domain softcap constants
#define SC_IN   0.057707801635558534f   // (2/50)*log2(e)
#define SC_C1   72.13475204444817f      // 50*log2(e)
#define SC_C2   144.26950408889634f     // 100*log2(e)

// Scratch (device globals: no cudaMalloc allowed)
__device__ uint32_t g_qkv16[(size_t)S_LEN * 1536];    // [S,1536w] fp16: Q(1024w)|K(256w)|V(256w)
__device__ uint32_t g_qk16[(size_t)S_LEN * QK16_LD];  // [S,1280w] fp16 post-rope: Q|K
__device__ uint32_t g_hs16[(size_t)S_LEN * 1024];     // hidden_states fp16
__device__ uint32_t g_w16[(size_t)3072 * 1024];       // wq|wk|wv fp16
__device__ uint32_t g_wo16[(size_t)2048 * 1024];      // wo fp16
__device__ uint32_t g_attn16[(size_t)S_LEN * 1024];   // attn out fp16

// ===========================================================================
// Helpers
// ===========================================================================
__device__ __forceinline__ uint32_t pk(float lo, float hi) {
    uint32_t d;
    asm("cvt.rn.f16x2.f32 %0, %1, %2;" : "=r"(d) : "f"(hi), "f"(lo));
    return d;
}
__device__ __forceinline__ float ex2f(float x) {
    float r;
    asm("ex2.approx.f32 %0, %1;" : "=f"(r) : "f"(x));
    return r;
}
__device__ __forceinline__ float rcpf(float x) {
    float r;
    asm("rcp.approx.f32 %0, %1;" : "=f"(r) : "f"(x));
    return r;
}
__device__ __forceinline__ void mma_f16(float* c, const uint32_t* a, const uint32_t* b) {
    asm volatile(
        "mma.sync.aligned.m16n8k16.row.col.f32.f16.f16.f32 "
        "{%0,%1,%2,%3}, {%4,%5,%6,%7}, {%8,%9}, {%0,%1,%2,%3};"
        : "+f"(c[0]), "+f"(c[1]), "+f"(c[2]), "+f"(c[3])
        : "r"(a[0]), "r"(a[1]), "r"(a[2]), "r"(a[3]), "r"(b[0]), "r"(b[1]));
}
__device__ __forceinline__ uint32_t smem_u32(const void* p) {
    uint32_t a;
    asm("{ .reg .u64 t; cvta.to.shared.u64 t, %1; cvt.u32.u64 %0, t; }"
        : "=r"(a) : "l"(p));
    return a;
}
#define LDSM4(r0, r1, r2, r3, addr) \
    asm volatile("ldmatrix.sync.aligned.m8n8.x4.shared.b16 {%0,%1,%2,%3}, [%4];" \
        : "=r"(r0), "=r"(r1), "=r"(r2), "=r"(r3) : "r"(addr))
#define LDSM4T(r0, r1, r2, r3, addr) \
    asm volatile("ldmatrix.sync.aligned.m8n8.x4.trans.shared.b16 {%0,%1,%2,%3}, [%4];" \
        : "=r"(r0), "=r"(r1), "=r"(r2), "=r"(r3) : "r"(addr))
#define CP_A16(saddr, gptr) \
    asm volatile("cp.async.cg.shared.global [%0], [%1], 16;" :: "r"(saddr), "l"(gptr))
#define CP_COMMIT() asm volatile("cp.async.commit_group;" ::: "memory")
#define CP_WAIT(n)  asm volatile("cp.async.wait_group %0;" :: "n"(n) : "memory")

// ---------------------------------------------------------------------------
// Fused f32 -> fp16x2 convert (one launch)
// ---------------------------------------------------------------------------
#define N_HS 2097152
#define N_WQ 1048576
#define N_WK 262144
#define N_WV 262144
#define N_WO 1048576
#define N_CVT (N_HS + N_WQ + N_WK + N_WV + N_WO)

__global__ void cvt_all(const float* __restrict__ hs, const float* __restrict__ wq,
                        const float* __restrict__ wk, const float* __restrict__ wv,
                        const float* __restrict__ wo,
                        uint32_t* __restrict__ hs16, uint32_t* __restrict__ w16,
                        uint32_t* __restrict__ wo16)
{
    int i = blockIdx.x * 256 + threadIdx.x;
    if (i >= N_CVT) return;
    const float* src; uint32_t* dst; int j = i;
    if (j < N_HS)                 { src = hs; dst = hs16; }
    else if ((j -= N_HS) < N_WQ)  { src = wq; dst = w16; }
    else if ((j -= N_WQ) < N_WK)  { src = wk; dst = w16 + (size_t)2048 * 1024; }
    else if ((j -= N_WK) < N_WV)  { src = wv; dst = w16 + (size_t)2560 * 1024; }
    else { j -= N_WV;               src = wo; dst = wo16; }
    float4 v = ((const float4*)src)[j];
    ((uint2*)dst)[j] = make_uint2(pk(v.x, v.y), pk(v.z, v.w));
}

// ===========================================================================
// FP16 GEMM (structure from R9; epilogue writes f32 or fp16 per flag)
// ===========================================================================
#define KC 64
#define STAGES 3
#define AST 16384
#define BST 16384
#define STG (AST + BST)
#define GEMM_SMEM (STAGES * STG)

__global__ __launch_bounds__(256, 2) void gemm_h(
    const __half* __restrict__ A, const __half* __restrict__ B,
    void* __restrict__ Cout, int Kd, int ldc, int f16out)
{
    extern __shared__ __align__(128) char smc[];
    const uint32_t sb = smem_u32(smc);

    const int tid  = threadIdx.x;
    const int lane = tid & 31;
    const int warp = tid >> 5;
    const int wm   = warp >> 1;
    const int wn   = warp & 1;
    const int bm   = blockIdx.y * 128;
    const int bnG  = blockIdx.x * 128;
    const int NC   = Kd / KC;

    const int lrow = tid >> 3;
    const int lc16 = tid & 7;
    const __half* Ag = A + (size_t)(bm + lrow) * Kd + lc16 * 8;
    const __half* Bg = B + (size_t)(bnG + lrow) * Kd + lc16 * 8;

    uint32_t so[4];
#pragma unroll
    for (int it = 0; it < 4; it++) {
        int row = lrow + it * 32;
        so[it] = (uint32_t)(row * 128 + ((lc16 ^ (row & 7)) << 4));
    }

    const int l15 = lane & 15;
    const int lh  = lane >> 4;
    int aRow[2], bRow[4];
#pragma unroll
    for (int mi = 0; mi < 2; mi++) aRow[mi] = wm * 32 + mi * 16 + l15;
#pragma unroll
    for (int nt = 0; nt < 4; nt++) bRow[nt] = wn * 64 + nt * 16 + l15;

    float acc[2][8][4];
#pragma unroll
    for (int i = 0; i < 2; i++)
#pragma unroll
        for (int j = 0; j < 8; j++)
#pragma unroll
            for (int e = 0; e < 4; e++) acc[i][j][e] = 0.f;

#pragma unroll
    for (int s = 0; s < STAGES - 1; s++) {
        const uint32_t sA = sb + s * STG;
        const uint32_t sB = sA + AST;
        const size_t ko = (size_t)s * KC;
#pragma unroll
        for (int it = 0; it < 4; it++) {
            CP_A16(sA + so[it], Ag + (size_t)(it * 32) * Kd + ko);
            CP_A16(sB + so[it], Bg + (size_t)(it * 32) * Kd + ko);
        }
        CP_COMMIT();
    }

    for (int ic = 0; ic < NC; ic++) {
        if (ic + STAGES - 1 < NC) {
            const int s = (ic + STAGES - 1) % STAGES;
            const uint32_t sA = sb + s * STG;
            const uint32_t sB = sA + AST;
            const size_t ko = (size_t)(ic + STAGES - 1) * KC;
#pragma unroll
            for (int it = 0; it < 4; it++) {
                CP_A16(sA + so[it], Ag + (size_t)(it * 32) * Kd + ko);
                CP_A16(sB + so[it], Bg + (size_t)(it * 32) * Kd + ko);
            }
        }
        CP_COMMIT();
        CP_WAIT(STAGES - 1);
        __syncthreads();

        const uint32_t sA = sb + (ic % STAGES) * STG;
        const uint32_t sB = sA + AST;

#pragma unroll
        for (int ki = 0; ki < 4; ki++) {
            const int kb = ki * 2 + lh;
            uint32_t af[2][4], bv[4][4];
#pragma unroll
            for (int mi = 0; mi < 2; mi++) {
                uint32_t ad = sA + aRow[mi] * 128 + (((kb ^ (aRow[mi] & 7))) << 4);
                LDSM4(af[mi][0], af[mi][1], af[mi][2], af[mi][3], ad);
            }
#pragma unroll
            for (int nt = 0; nt < 4; nt++) {
                uint32_t bd = sB + bRow[nt] * 128 + (((kb ^ (bRow[nt] & 7))) << 4);
                LDSM4(bv[nt][0], bv[nt][1], bv[nt][2], bv[nt][3], bd);
            }
#pragma unroll
            for (int mi = 0; mi < 2; mi++)
#pragma unroll
                for (int j = 0; j < 8; j++) {
                    uint32_t bf[2] = { bv[j >> 1][(j & 1)], bv[j >> 1][2 + (j & 1)] };
                    mma_f16(acc[mi][j], af[mi], bf);
                }
        }
        __syncthreads();
    }

    const int g = lane >> 2, t = lane & 3;
    if (f16out) {
        uint32_t* C16 = (uint32_t*)Cout;
        const int ldw = ldc >> 1;   // words per row
#pragma unroll
        for (int mi = 0; mi < 2; mi++)
#pragma unroll
            for (int j = 0; j < 8; j++) {
                const int row = bm + wm * 32 + mi * 16 + g;
                const int colw = (bnG + wn * 64 + j * 8 + t * 2) >> 1;
                C16[(size_t)row * ldw + colw]       = pk(acc[mi][j][0], acc[mi][j][1]);
                C16[(size_t)(row + 8) * ldw + colw] = pk(acc[mi][j][2], acc[mi][j][3]);
            }
    } else {
        float* C = (float*)Cout;
#pragma unroll
        for (int mi = 0; mi < 2; mi++)
#pragma unroll
            for (int j = 0; j < 8; j++) {
                const int row = bm + wm * 32 + mi * 16 + g;
                const int col = bnG + wn * 64 + j * 8 + t * 2;
                *(float2*)(C + (size_t)row * ldc + col) =
                    make_float2(acc[mi][j][0], acc[mi][j][1]);
                *(float2*)(C + (size_t)(row + 8) * ldc + col) =
                    make_float2(acc[mi][j][2], acc[mi][j][3]);
            }
    }
}

// ---------------------------------------------------------------------------
// RoPE + Q scale: reads fp16 qkv16 (Q,K), writes g_qk16. V untouched
// (attention reads V straight from g_qkv16).
// ---------------------------------------------------------------------------
__global__ void rope_pack(const uint32_t* __restrict__ qkv16,
                          uint32_t* __restrict__ qk16,
                          const float* __restrict__ cosp, const float* __restrict__ sinp)
{
    const int s = blockIdx.x;
    const float* c  = cosp + (size_t)s * DH;
    const float* sn = sinp + (size_t)s * DH;
    const uint32_t* row = qkv16 + (size_t)s * 1536;
    uint32_t* orow = qk16 + (size_t)s * QK16_LD;
    for (int i = threadIdx.x; i < 20 * 32; i += blockDim.x) {
        int hh = i >> 5;
        int c0 = i & 31;
        int d0 = 2 * c0;
        int base = (hh < 16) ? hh * 64 : (1024 + (hh - 16) * 64);
        float2 x1 = __half22float2(*(const __half2*)&row[base + c0]);
        float2 x2 = __half22float2(*(const __half2*)&row[base + 32 + c0]);
        float y1a = x1.x * c[d0]      - x2.x * sn[d0];
        float y1b = x1.y * c[d0 + 1]  - x2.y * sn[d0 + 1];
        float y2a = x2.x * c[d0 + 64] + x1.x * sn[d0 + 64];
        float y2b = x2.y * c[d0 + 65] + x1.y * sn[d0 + 65];
        if (hh < 16) { y1a *= Q_SCALE; y1b *= Q_SCALE; y2a *= Q_SCALE; y2b *= Q_SCALE; }
        orow[base + c0]      = pk(y1a, y1b);
        orow[base + 32 + c0] = pk(y2a, y2b);
    }
}

// ===========================================================================
// Flash attention: EXACT Round-10 structure (705 us best). Only change:
// V is read directly from g_qkv16 (row stride 6144 B).
// ===========================================================================
#define ATTN_SMEM 114688
#define SQ_OFF 0
#define SK_OFF 32768
#define SV_OFF 65536
#define SP_OFF 98304

__global__ __launch_bounds__(256, 2) void attn_mma(
    const uint32_t* __restrict__ qk16, const uint32_t* __restrict__ qkv16,
    uint32_t* __restrict__ out16)
{
    extern __shared__ __align__(128) char sm[];
    const uint32_t sb = smem_u32(sm);
    const uint32_t sQ = sb + SQ_OFF;

    const int tid  = threadIdx.x;
    const int lane = tid & 31;
    const int warp = tid >> 5;
    const int qb   = (int)gridDim.x - 1 - (int)blockIdx.x;
    const int h    = blockIdx.y;
    const int kvg  = h >> 2;

    const int g = lane >> 2, t = lane & 3;
    const int l15 = lane & 15, lh = lane >> 4;
    const int e7 = l15 & 7;

    const char* Qg = (const char*)(qk16 + (size_t)h * 64);           // stride 5120B
    const char* Kg = (const char*)(qk16 + 1024 + (size_t)kvg * 64);  // stride 5120B
    const char* Vg = (const char*)(qkv16 + 1280 + (size_t)kvg * 64); // stride 6144B

#pragma unroll
    for (int i = 0; i < 8; i++) {
        int idx = tid + i * 256;
        int row = idx >> 4, u = idx & 15;
        CP_A16(sQ + row * 256 + ((u ^ (row & 7)) << 4),
               Qg + (size_t)(qb * 128 + row) * 5120 + u * 16);
    }
#pragma unroll
    for (int i = 0; i < 4; i++) {
        int idx = tid + i * 256;
        int row = idx >> 4, u = idx & 15;
        uint32_t so = row * 256 + ((u ^ (row & 7)) << 4);
        CP_A16(sb + SK_OFF + so, Kg + (size_t)row * 5120 + u * 16);
        CP_A16(sb + SV_OFF + so, Vg + (size_t)row * 6144 + u * 16);
    }
    CP_COMMIT();

    float oacc[16][4], lacc[4];
#pragma unroll
    for (int i = 0; i < 16; i++)
#pragma unroll
        for (int e = 0; e < 4; e++) oacc[i][e] = 0.f;
#pragma unroll
    for (int e = 0; e < 4; e++) lacc[e] = 0.f;
    float m0 = -1e30f, m1 = -1e30f;

    const int qr0 = qb * 128 + warp * 16 + g;
    const int ntiles = 2 * qb + 2;

    // hoisted bases (kt-invariant)
    const uint32_t qbase = sQ + (warp * 16 + l15) * 256;
    const uint32_t kofsL = (uint32_t)(l15 * 256);
    const uint32_t prd_b = sb + SP_OFF + warp * 2048 + l15 * 128;
    const uint32_t ones2[2] = { 0x3C003C00u, 0x3C003C00u };

    // P store addresses (kt-invariant): 8 nt slots
    uint32_t pst[8];
#pragma unroll
    for (int nt = 0; nt < 8; nt++)
        pst[nt] = (uint32_t)(SP_OFF + warp * 2048 + g * 128 + ((nt ^ (g & 7)) << 4) + t * 4);

    for (int kt = 0; kt < ntiles; kt++) {
        CP_WAIT(0);
        __syncthreads();

        if (kt + 1 < ntiles) {
            const uint32_t dK = sb + SK_OFF + ((kt + 1) & 1) * 16384;
            const uint32_t dV = sb + SV_OFF + ((kt + 1) & 1) * 16384;
#pragma unroll
            for (int i = 0; i < 4; i++) {
                int idx = tid + i * 256;
                int row = idx >> 4, u = idx & 15;
                uint32_t so = row * 256 + ((u ^ (row & 7)) << 4);
                CP_A16(dK + so, Kg + (size_t)((kt + 1) * 64 + row) * 5120 + u * 16);
                CP_A16(dV + so, Vg + (size_t)((kt + 1) * 64 + row) * 6144 + u * 16);
            }
            CP_COMMIT();
        }

        const uint32_t cK = sb + SK_OFF + (kt & 1) * 16384;
        const uint32_t cV = sb + SV_OFF + (kt & 1) * 16384;

        // ---- QK ----
        float acc[8][4];
#pragma unroll
        for (int nt = 0; nt < 8; nt++)
#pragma unroll
            for (int e = 0; e < 4; e++) acc[nt][e] = 0.f;

#pragma unroll
        for (int ki = 0; ki < 8; ki++) {
            const uint32_t xo = (uint32_t)(((ki * 2 + lh) ^ e7) << 4);
            uint32_t af[4];
            LDSM4(af[0], af[1], af[2], af[3], qbase + xo);
            const uint32_t kb0 = cK + kofsL + xo;
#pragma unroll
            for (int ntp = 0; ntp < 4; ntp++) {
                uint32_t r0, r1, r2, r3;
                LDSM4(r0, r1, r2, r3, kb0 + ntp * 4096);
                uint32_t bf0[2] = { r0, r2 };
                uint32_t bf1[2] = { r1, r3 };
                mma_f16(acc[2 * ntp],     af, bf0);
                mma_f16(acc[2 * ntp + 1], af, bf1);
            }
        }

        // ---- softcap (log2 domain) + causal + row max (R10 form) ----
        const bool diag = (kt >= 2 * qb);
        float mt0 = -1e30f, mt1 = -1e30f;
#pragma unroll
        for (int nt = 0; nt < 8; nt++) {
#pragma unroll
            for (int e = 0; e < 4; e++) {
                float w = ex2f(acc[nt][e] * SC_IN);
                float v = fmaf(-SC_C2, rcpf(w + 1.f), SC_C1);
                if (diag) {
                    int kc = kt * 64 + nt * 8 + 2 * t + (e & 1);
                    int qr = qr0 + ((e >> 1) << 3);
                    if (kc > qr) v = -1e30f;
                }
                acc[nt][e] = v;
                if (e < 2) mt0 = fmaxf(mt0, v); else mt1 = fmaxf(mt1, v);
            }
        }
        mt0 = fmaxf(mt0, __shfl_xor_sync(0xffffffffu, mt0, 1));
        mt0 = fmaxf(mt0, __shfl_xor_sync(0xffffffffu, mt0, 2));
        mt1 = fmaxf(mt1, __shfl_xor_sync(0xffffffffu, mt1, 1));
        mt1 = fmaxf(mt1, __shfl_xor_sync(0xffffffffu, mt1, 2));

        const bool nochg = (mt0 <= m0) && (mt1 <= m1);
        if (!__all_sync(0xffffffffu, nochg)) {
            const float mn0 = fmaxf(m0, mt0), mn1 = fmaxf(m1, mt1);
            const float al0 = ex2f(m0 - mn0), al1 = ex2f(m1 - mn1);
            m0 = mn0; m1 = mn1;
#pragma unroll
            for (int ni = 0; ni < 16; ni++) {
                oacc[ni][0] *= al0; oacc[ni][1] *= al0;
                oacc[ni][2] *= al1; oacc[ni][3] *= al1;
            }
            lacc[0] *= al0; lacc[1] *= al0;
            lacc[2] *= al1; lacc[3] *= al1;
        }

        // ---- p = ex2(v - m), pack, store to P smem ----
#pragma unroll
        for (int nt = 0; nt < 8; nt++) {
            float p0 = ex2f(acc[nt][0] - m0);
            float p1 = ex2f(acc[nt][1] - m0);
            float p2 = ex2f(acc[nt][2] - m1);
            float p3 = ex2f(acc[nt][3] - m1);
            *(uint32_t*)(sm + pst[nt])             = pk(p0, p1);
            *(uint32_t*)(sm + pst[nt] + 8 * 128)   = pk(p2, p3);
        }
        __syncwarp();

        // ---- PV + ones-MMA row sum ----
#pragma unroll
        for (int ki = 0; ki < 4; ki++) {
            const uint32_t xo = (uint32_t)(((ki * 2 + lh) ^ e7) << 4);
            uint32_t af[4];
            LDSM4(af[0], af[1], af[2], af[3], prd_b + xo);
            mma_f16(lacc, af, ones2);
            const uint32_t vb0 = cV + ki * 4096 + kofsL;
#pragma unroll
            for (int nip = 0; nip < 8; nip++) {
                uint32_t r0, r1, r2, r3;
                uint32_t va = vb0 + ((uint32_t)((nip * 2 + lh) ^ e7) << 4);
                LDSM4T(r0, r1, r2, r3, va);
                uint32_t bf0[2] = { r0, r1 };
                uint32_t bf1[2] = { r2, r3 };
                mma_f16(oacc[2 * nip],     af, bf0);
                mma_f16(oacc[2 * nip + 1], af, bf1);
            }
        }
    }

    // ---- epilogue: fp16 output, l from lacc ----
    const float inv0 = __fdividef(1.f, lacc[0]);
    const float inv1 = __fdividef(1.f, lacc[2]);
    uint32_t* o0 = out16 + (size_t)qr0 * 1024 + h * 64 + t;
    uint32_t* o1 = out16 + (size_t)(qr0 + 8) * 1024 + h * 64 + t;
#pragma unroll
    for (int ni = 0; ni < 16; ni++) {
        o0[ni * 4] = pk(oacc[ni][0] * inv0, oacc[ni][1] * inv0);
        o1[ni * 4] = pk(oacc[ni][2] * inv1, oacc[ni][3] * inv1);
    }
}

// ---------------------------------------------------------------------------
// Inputs (metadata order): hidden_states, cos, sin, attention_mask, wq, wk, wv, wo
// ---------------------------------------------------------------------------
extern "C" void kernel_launch(void* const* d_in, const int* in_sizes, int n_in,
                              void* d_out, int out_size)
{
    const float* hs   = (const float*)d_in[0];
    const float* cosp = (const float*)d_in[1];
    const float* sinp = (const float*)d_in[2];
    const float* wq   = (const float*)d_in[4];
    const float* wk   = (const float*)d_in[5];
    const float* wv   = (const float*)d_in[6];
    const float* wo   = (const float*)d_in[7];
    float* out = (float*)d_out;

    uint32_t* qkv16 = nullptr; uint32_t* qk16 = nullptr;
    uint32_t* hs16 = nullptr; uint32_t* w16 = nullptr;
    uint32_t* wo16 = nullptr; uint32_t* attn16 = nullptr;
    cudaGetSymbolAddress((void**)&qkv16,  g_qkv16);
    cudaGetSymbolAddress((void**)&qk16,   g_qk16);
    cudaGetSymbolAddress((void**)&hs16,   g_hs16);
    cudaGetSymbolAddress((void**)&w16,    g_w16);
    cudaGetSymbolAddress((void**)&wo16,   g_wo16);
    cudaGetSymbolAddress((void**)&attn16, g_attn16);

    cudaFuncSetAttribute(gemm_h, cudaFuncAttributeMaxDynamicSharedMemorySize, GEMM_SMEM);
    cudaFuncSetAttribute(attn_mma, cudaFuncAttributeMaxDynamicSharedMemorySize, ATTN_SMEM);

    dim3 blk(256);
    cvt_all<<<(N_CVT + 255) / 256, blk>>>(hs, wq, wk, wv, wo, hs16, w16, wo16);
    // QKV projection -> fp16 directly
    gemm_h<<<dim3(3072 / 128, S_LEN / 128), blk, GEMM_SMEM>>>(
        (const __half*)hs16, (const __half*)w16, qkv16, HID, 3072, 1);
    rope_pack<<<S_LEN, 256>>>(qkv16, qk16, cosp, sinp);
    attn_mma<<<dim3(S_LEN / 128, NH), blk, ATTN_SMEM>>>(qk16, qkv16, attn16);
    // Output projection -> f32
    gemm_h<<<dim3(2048 / 128, S_LEN / 128), blk, GEMM_SMEM>>>(
        (const __half*)attn16, (const __half*)wo16, out, HID, HID, 0);
}

// round 14
// speedup vs baseline: 1.5506x; 1.0554x over previous
#include <cuda_runtime.h>
#include <cuda_bf16.h>
#include <cuda_fp16.h>
#include <cstdint>

#define S_LEN   4096
#define HID     2048
#define NH      16
#define NKV     4
#define DH      128
#define QKV_LD  3072
#define QK16_LD 1280
#define Q_SCALE 0.08838834764831845f
#define CAP     50.0f
// exact log2-domain softcap constants (fallback path)
#define SC_IN   0.057707801635558534f   // (2/50)*log2(e)
#define SC_C1   72.13475204444817f      // 50*log2(e)
#define SC_C2   144.26950408889634f     // 100*log2(e)
// polynomial softcap (log2 output): v = s*(PL - s^2*(P3 - P5*s^2))
#define PL  1.4426950408889634f         // log2(e)
#define P3  1.9235933878519513e-4f      // log2(e)/7500
#define P5  3.0777494205631223e-8f      // 2*log2(e)/93750000
#define POLY_LIM 15.0f

// Scratch (device globals: no cudaMalloc allowed)
__device__ float    g_qkv[(size_t)S_LEN * QKV_LD];
__device__ uint32_t g_qk16[(size_t)S_LEN * QK16_LD];
__device__ uint32_t g_v16[(size_t)S_LEN * 256];
__device__ uint32_t g_hs16[(size_t)S_LEN * 1024];
__device__ uint32_t g_w16[(size_t)3072 * 1024];
__device__ uint32_t g_wo16[(size_t)2048 * 1024];
__device__ uint32_t g_attn16[(size_t)S_LEN * 1024];

// ===========================================================================
// Helpers
// ===========================================================================
__device__ __forceinline__ uint32_t pk(float lo, float hi) {
    uint32_t d;
    asm("cvt.rn.f16x2.f32 %0, %1, %2;" : "=r"(d) : "f"(hi), "f"(lo));
    return d;
}
__device__ __forceinline__ float ex2f(float x) {
    float r;
    asm("ex2.approx.f32 %0, %1;" : "=f"(r) : "f"(x));
    return r;
}
__device__ __forceinline__ float rcpf(float x) {
    float r;
    asm("rcp.approx.f32 %0, %1;" : "=f"(r) : "f"(x));
    return r;
}
__device__ __forceinline__ void mma_f16(float* c, const uint32_t* a, const uint32_t* b) {
    asm volatile(
        "mma.sync.aligned.m16n8k16.row.col.f32.f16.f16.f32 "
        "{%0,%1,%2,%3}, {%4,%5,%6,%7}, {%8,%9}, {%0,%1,%2,%3};"
        : "+f"(c[0]), "+f"(c[1]), "+f"(c[2]), "+f"(c[3])
        : "r"(a[0]), "r"(a[1]), "r"(a[2]), "r"(a[3]), "r"(b[0]), "r"(b[1]));
}
__device__ __forceinline__ uint32_t smem_u32(const void* p) {
    uint32_t a;
    asm("{ .reg .u64 t; cvta.to.shared.u64 t, %1; cvt.u32.u64 %0, t; }"
        : "=r"(a) : "l"(p));
    return a;
}
#define LDSM4(r0, r1, r2, r3, addr) \
    asm volatile("ldmatrix.sync.aligned.m8n8.x4.shared.b16 {%0,%1,%2,%3}, [%4];" \
        : "=r"(r0), "=r"(r1), "=r"(r2), "=r"(r3) : "r"(addr))
#define LDSM4T(r0, r1, r2, r3, addr) \
    asm volatile("ldmatrix.sync.aligned.m8n8.x4.trans.shared.b16 {%0,%1,%2,%3}, [%4];" \
        : "=r"(r0), "=r"(r1), "=r"(r2), "=r"(r3) : "r"(addr))
#define CP_A16(saddr, gptr) \
    asm volatile("cp.async.cg.shared.global [%0], [%1], 16;" :: "r"(saddr), "l"(gptr))
#define CP_COMMIT() asm volatile("cp.async.commit_group;" ::: "memory")
#define CP_WAIT(n)  asm volatile("cp.async.wait_group %0;" :: "n"(n) : "memory")

// ---------------------------------------------------------------------------
// Fused f32 -> fp16x2 convert (one launch)
// ---------------------------------------------------------------------------
#define N_HS 2097152
#define N_WQ 1048576
#define N_WK 262144
#define N_WV 262144
#define N_WO 1048576
#define N_CVT (N_HS + N_WQ + N_WK + N_WV + N_WO)

__global__ void cvt_all(const float* __restrict__ hs, const float* __restrict__ wq,
                        const float* __restrict__ wk, const float* __restrict__ wv,
                        const float* __restrict__ wo,
                        uint32_t* __restrict__ hs16, uint32_t* __restrict__ w16,
                        uint32_t* __restrict__ wo16)
{
    int i = blockIdx.x * 256 + threadIdx.x;
    if (i >= N_CVT) return;
    const float* src; uint32_t* dst; int j = i;
    if (j < N_HS)                 { src = hs; dst = hs16; }
    else if ((j -= N_HS) < N_WQ)  { src = wq; dst = w16; }
    else if ((j -= N_WQ) < N_WK)  { src = wk; dst = w16 + (size_t)2048 * 1024; }
    else if ((j -= N_WK) < N_WV)  { src = wv; dst = w16 + (size_t)2560 * 1024; }
    else { j -= N_WV;               src = wo; dst = wo16; }
    float4 v = ((const float4*)src)[j];
    ((uint2*)dst)[j] = make_uint2(pk(v.x, v.y), pk(v.z, v.w));
}

// ===========================================================================
// FP16 GEMM (R9/R10 form, f32 out)
// ===========================================================================
#define KC 64
#define STAGES 3
#define AST 16384
#define BST 16384
#define STG (AST + BST)
#define GEMM_SMEM (STAGES * STG)

__global__ __launch_bounds__(256, 2) void gemm_h(
    const __half* __restrict__ A, const __half* __restrict__ B,
    float* __restrict__ C, int Kd, int ldc)
{
    extern __shared__ __align__(128) char smc[];
    const uint32_t sb = smem_u32(smc);

    const int tid  = threadIdx.x;
    const int lane = tid & 31;
    const int warp = tid >> 5;
    const int wm   = warp >> 1;
    const int wn   = warp & 1;
    const int bm   = blockIdx.y * 128;
    const int bnG  = blockIdx.x * 128;
    const int NC   = Kd / KC;

    const int lrow = tid >> 3;
    const int lc16 = tid & 7;
    const __half* Ag = A + (size_t)(bm + lrow) * Kd + lc16 * 8;
    const __half* Bg = B + (size_t)(bnG + lrow) * Kd + lc16 * 8;

    uint32_t so[4];
#pragma unroll
    for (int it = 0; it < 4; it++) {
        int row = lrow + it * 32;
        so[it] = (uint32_t)(row * 128 + ((lc16 ^ (row & 7)) << 4));
    }

    const int l15 = lane & 15;
    const int lh  = lane >> 4;
    int aRow[2], bRow[4];
#pragma unroll
    for (int mi = 0; mi < 2; mi++) aRow[mi] = wm * 32 + mi * 16 + l15;
#pragma unroll
    for (int nt = 0; nt < 4; nt++) bRow[nt] = wn * 64 + nt * 16 + l15;

    float acc[2][8][4];
#pragma unroll
    for (int i = 0; i < 2; i++)
#pragma unroll
        for (int j = 0; j < 8; j++)
#pragma unroll
            for (int e = 0; e < 4; e++) acc[i][j][e] = 0.f;

#pragma unroll
    for (int s = 0; s < STAGES - 1; s++) {
        const uint32_t sA = sb + s * STG;
        const uint32_t sB = sA + AST;
        const size_t ko = (size_t)s * KC;
#pragma unroll
        for (int it = 0; it < 4; it++) {
            CP_A16(sA + so[it], Ag + (size_t)(it * 32) * Kd + ko);
            CP_A16(sB + so[it], Bg + (size_t)(it * 32) * Kd + ko);
        }
        CP_COMMIT();
    }

    for (int ic = 0; ic < NC; ic++) {
        if (ic + STAGES - 1 < NC) {
            const int s = (ic + STAGES - 1) % STAGES;
            const uint32_t sA = sb + s * STG;
            const uint32_t sB = sA + AST;
            const size_t ko = (size_t)(ic + STAGES - 1) * KC;
#pragma unroll
            for (int it = 0; it < 4; it++) {
                CP_A16(sA + so[it], Ag + (size_t)(it * 32) * Kd + ko);
                CP_A16(sB + so[it], Bg + (size_t)(it * 32) * Kd + ko);
            }
        }
        CP_COMMIT();
        CP_WAIT(STAGES - 1);
        __syncthreads();

        const uint32_t sA = sb + (ic % STAGES) * STG;
        const uint32_t sB = sA + AST;

#pragma unroll
        for (int ki = 0; ki < 4; ki++) {
            const int kb = ki * 2 + lh;
            uint32_t af[2][4], bv[4][4];
#pragma unroll
            for (int mi = 0; mi < 2; mi++) {
                uint32_t ad = sA + aRow[mi] * 128 + (((kb ^ (aRow[mi] & 7))) << 4);
                LDSM4(af[mi][0], af[mi][1], af[mi][2], af[mi][3], ad);
            }
#pragma unroll
            for (int nt = 0; nt < 4; nt++) {
                uint32_t bd = sB + bRow[nt] * 128 + (((kb ^ (bRow[nt] & 7))) << 4);
                LDSM4(bv[nt][0], bv[nt][1], bv[nt][2], bv[nt][3], bd);
            }
#pragma unroll
            for (int mi = 0; mi < 2; mi++)
#pragma unroll
                for (int j = 0; j < 8; j++) {
                    uint32_t bf[2] = { bv[j >> 1][(j & 1)], bv[j >> 1][2 + (j & 1)] };
                    mma_f16(acc[mi][j], af[mi], bf);
                }
        }
        __syncthreads();
    }

    const int g = lane >> 2, t = lane & 3;
#pragma unroll
    for (int mi = 0; mi < 2; mi++)
#pragma unroll
        for (int j = 0; j < 8; j++) {
            const int row = bm + wm * 32 + mi * 16 + g;
            const int col = bnG + wn * 64 + j * 8 + t * 2;
            float* p0 = C + (size_t)row * ldc + col;
            float* p1 = C + (size_t)(row + 8) * ldc + col;
            *(float2*)p0 = make_float2(acc[mi][j][0], acc[mi][j][1]);
            *(float2*)p1 = make_float2(acc[mi][j][2], acc[mi][j][3]);
        }
}

// ---------------------------------------------------------------------------
// RoPE + Q scale -> g_qk16; V -> g_v16 (R10 form)
// ---------------------------------------------------------------------------
__global__ void rope_pack(const float* __restrict__ qkv,
                          uint32_t* __restrict__ qk16, uint32_t* __restrict__ v16,
                          const float* __restrict__ cosp, const float* __restrict__ sinp)
{
    const int s = blockIdx.x;
    const float* c  = cosp + (size_t)s * DH;
    const float* sn = sinp + (size_t)s * DH;
    const float* row = qkv + (size_t)s * QKV_LD;
    uint32_t* orow = qk16 + (size_t)s * QK16_LD;
    uint32_t* vrow = v16 + (size_t)s * 256;
    for (int i = threadIdx.x; i < 24 * 32; i += blockDim.x) {
        int hh = i >> 5;
        int c0 = i & 31;
        if (hh < 20) {
            int d0 = 2 * c0;
            int base = (hh < 16) ? hh * 128 : (2048 + (hh - 16) * 128);
            float x1a = row[base + d0],      x1b = row[base + d0 + 1];
            float x2a = row[base + d0 + 64], x2b = row[base + d0 + 65];
            float y1a = x1a * c[d0]      - x2a * sn[d0];
            float y1b = x1b * c[d0 + 1]  - x2b * sn[d0 + 1];
            float y2a = x2a * c[d0 + 64] + x1a * sn[d0 + 64];
            float y2b = x2b * c[d0 + 65] + x1b * sn[d0 + 65];
            if (hh < 16) { y1a *= Q_SCALE; y1b *= Q_SCALE; y2a *= Q_SCALE; y2b *= Q_SCALE; }
            int obase = (hh < 16) ? hh * 64 : (1024 + (hh - 16) * 64);
            orow[obase + c0]      = pk(y1a, y1b);
            orow[obase + 32 + c0] = pk(y2a, y2b);
        } else {
            int base = 2560 + (hh - 20) * 128;
            int obase = (hh - 20) * 64;
            vrow[obase + c0]      = pk(row[base + 2 * c0],      row[base + 2 * c0 + 1]);
            vrow[obase + 32 + c0] = pk(row[base + 64 + 2 * c0], row[base + 64 + 2 * c0 + 1]);
        }
    }
}

// ===========================================================================
// Flash attention: R10 structure + polynomial softcap fast path (0 MUFU)
// + vote-gated shfl max reduction. 2 CTAs/SM.
// ===========================================================================
#define ATTN_SMEM 114688
#define SQ_OFF 0
#define SK_OFF 32768
#define SV_OFF 65536
#define SP_OFF 98304

__global__ __launch_bounds__(256, 2) void attn_mma(
    const uint32_t* __restrict__ qk16, const uint32_t* __restrict__ v16,
    uint32_t* __restrict__ out16)
{
    extern __shared__ __align__(128) char sm[];
    const uint32_t sb = smem_u32(sm);
    const uint32_t sQ = sb + SQ_OFF;

    const int tid  = threadIdx.x;
    const int lane = tid & 31;
    const int warp = tid >> 5;
    const int qb   = (int)gridDim.x - 1 - (int)blockIdx.x;
    const int h    = blockIdx.y;
    const int kvg  = h >> 2;

    const int g = lane >> 2, t = lane & 3;
    const int l15 = lane & 15, lh = lane >> 4;
    const int e7 = l15 & 7;

    const char* Qg = (const char*)(qk16 + (size_t)h * 64);
    const char* Kg = (const char*)(qk16 + 1024 + (size_t)kvg * 64);
    const char* Vg = (const char*)(v16 + (size_t)kvg * 64);

#pragma unroll
    for (int i = 0; i < 8; i++) {
        int idx = tid + i * 256;
        int row = idx >> 4, u = idx & 15;
        CP_A16(sQ + row * 256 + ((u ^ (row & 7)) << 4),
               Qg + (size_t)(qb * 128 + row) * 5120 + u * 16);
    }
#pragma unroll
    for (int i = 0; i < 4; i++) {
        int idx = tid + i * 256;
        int row = idx >> 4, u = idx & 15;
        uint32_t so = row * 256 + ((u ^ (row & 7)) << 4);
        CP_A16(sb + SK_OFF + so, Kg + (size_t)row * 5120 + u * 16);
        CP_A16(sb + SV_OFF + so, Vg + (size_t)row * 1024 + u * 16);
    }
    CP_COMMIT();

    float oacc[16][4], lacc[4];
#pragma unroll
    for (int i = 0; i < 16; i++)
#pragma unroll
        for (int e = 0; e < 4; e++) oacc[i][e] = 0.f;
#pragma unroll
    for (int e = 0; e < 4; e++) lacc[e] = 0.f;
    float m0 = -1e30f, m1 = -1e30f;

    const int qr0 = qb * 128 + warp * 16 + g;
    const int ntiles = 2 * qb + 2;

    // hoisted bases (kt-invariant)
    const uint32_t qbase = sQ + (warp * 16 + l15) * 256;
    const uint32_t kofsL = (uint32_t)(l15 * 256);
    const uint32_t prd_b = sb + SP_OFF + warp * 2048 + l15 * 128;
    const uint32_t ones2[2] = { 0x3C003C00u, 0x3C003C00u };

    uint32_t pst[8];
#pragma unroll
    for (int nt = 0; nt < 8; nt++)
        pst[nt] = (uint32_t)(SP_OFF + warp * 2048 + g * 128 + ((nt ^ (g & 7)) << 4) + t * 4);

    for (int kt = 0; kt < ntiles; kt++) {
        CP_WAIT(0);
        __syncthreads();

        if (kt + 1 < ntiles) {
            const uint32_t dK = sb + SK_OFF + ((kt + 1) & 1) * 16384;
            const uint32_t dV = sb + SV_OFF + ((kt + 1) & 1) * 16384;
#pragma unroll
            for (int i = 0; i < 4; i++) {
                int idx = tid + i * 256;
                int row = idx >> 4, u = idx & 15;
                uint32_t so = row * 256 + ((u ^ (row & 7)) << 4);
                CP_A16(dK + so, Kg + (size_t)((kt + 1) * 64 + row) * 5120 + u * 16);
                CP_A16(dV + so, Vg + (size_t)((kt + 1) * 64 + row) * 1024 + u * 16);
            }
            CP_COMMIT();
        }

        const uint32_t cK = sb + SK_OFF + (kt & 1) * 16384;
        const uint32_t cV = sb + SV_OFF + (kt & 1) * 16384;

        // ---- QK ----
        float acc[8][4];
#pragma unroll
        for (int nt = 0; nt < 8; nt++)
#pragma unroll
            for (int e = 0; e < 4; e++) acc[nt][e] = 0.f;

#pragma unroll
        for (int ki = 0; ki < 8; ki++) {
            const uint32_t xo = (uint32_t)(((ki * 2 + lh) ^ e7) << 4);
            uint32_t af[4];
            LDSM4(af[0], af[1], af[2], af[3], qbase + xo);
            const uint32_t kb0 = cK + kofsL + xo;
#pragma unroll
            for (int ntp = 0; ntp < 4; ntp++) {
                uint32_t r0, r1, r2, r3;
                LDSM4(r0, r1, r2, r3, kb0 + ntp * 4096);
                uint32_t bf0[2] = { r0, r2 };
                uint32_t bf1[2] = { r1, r3 };
                mma_f16(acc[2 * ntp],     af, bf0);
                mma_f16(acc[2 * ntp + 1], af, bf1);
            }
        }

        // ---- softcap: polynomial fast path (0 MUFU) with exact fallback ----
        float ma = 0.f;
#pragma unroll
        for (int nt = 0; nt < 8; nt++)
#pragma unroll
            for (int e = 0; e < 4; e++) ma = fmaxf(ma, fabsf(acc[nt][e]));
        const bool poly = __all_sync(0xffffffffu, ma < POLY_LIM);

        const bool diag = (kt >= 2 * qb);
        float mt0 = -1e30f, mt1 = -1e30f;
        if (poly) {
#pragma unroll
            for (int nt = 0; nt < 8; nt++) {
#pragma unroll
                for (int e = 0; e < 4; e++) {
                    float s  = acc[nt][e];
                    float s2 = s * s;
                    float tt = fmaf(-P5, s2, P3);
                    float v  = s * fmaf(-s2, tt, PL);
                    if (diag) {
                        int kc = kt * 64 + nt * 8 + 2 * t + (e & 1);
                        int qr = qr0 + ((e >> 1) << 3);
                        if (kc > qr) v = -1e30f;
                    }
                    acc[nt][e] = v;
                    if (e < 2) mt0 = fmaxf(mt0, v); else mt1 = fmaxf(mt1, v);
                }
            }
        } else {
#pragma unroll
            for (int nt = 0; nt < 8; nt++) {
#pragma unroll
                for (int e = 0; e < 4; e++) {
                    float w = ex2f(acc[nt][e] * SC_IN);
                    float v = fmaf(-SC_C2, rcpf(w + 1.f), SC_C1);
                    if (diag) {
                        int kc = kt * 64 + nt * 8 + 2 * t + (e & 1);
                        int qr = qr0 + ((e >> 1) << 3);
                        if (kc > qr) v = -1e30f;
                    }
                    acc[nt][e] = v;
                    if (e < 2) mt0 = fmaxf(mt0, v); else mt1 = fmaxf(mt1, v);
                }
            }
        }

        // ---- vote-gated max reduction + rescale ----
        const bool need = (mt0 > m0) || (mt1 > m1);
        if (__any_sync(0xffffffffu, need)) {
            mt0 = fmaxf(mt0, __shfl_xor_sync(0xffffffffu, mt0, 1));
            mt0 = fmaxf(mt0, __shfl_xor_sync(0xffffffffu, mt0, 2));
            mt1 = fmaxf(mt1, __shfl_xor_sync(0xffffffffu, mt1, 1));
            mt1 = fmaxf(mt1, __shfl_xor_sync(0xffffffffu, mt1, 2));
            const float mn0 = fmaxf(m0, mt0), mn1 = fmaxf(m1, mt1);
            const float al0 = ex2f(m0 - mn0), al1 = ex2f(m1 - mn1);
            m0 = mn0; m1 = mn1;
#pragma unroll
            for (int ni = 0; ni < 16; ni++) {
                oacc[ni][0] *= al0; oacc[ni][1] *= al0;
                oacc[ni][2] *= al1; oacc[ni][3] *= al1;
            }
            lacc[0] *= al0; lacc[1] *= al0;
            lacc[2] *= al1; lacc[3] *= al1;
        }

        // ---- p = ex2(v - m), pack, store to P smem ----
#pragma unroll
        for (int nt = 0; nt < 8; nt++) {
            float p0 = ex2f(acc[nt][0] - m0);
            float p1 = ex2f(acc[nt][1] - m0);
            float p2 = ex2f(acc[nt][2] - m1);
            float p3 = ex2f(acc[nt][3] - m1);
            *(uint32_t*)(sm + pst[nt])             = pk(p0, p1);
            *(uint32_t*)(sm + pst[nt] + 8 * 128)   = pk(p2, p3);
        }
        __syncwarp();

        // ---- PV + ones-MMA row sum ----
#pragma unroll
        for (int ki = 0; ki < 4; ki++) {
            const uint32_t xo = (uint32_t)(((ki * 2 + lh) ^ e7) << 4);
            uint32_t af[4];
            LDSM4(af[0], af[1], af[2], af[3], prd_b + xo);
            mma_f16(lacc, af, ones2);
            const uint32_t vb0 = cV + ki * 4096 + kofsL;
#pragma unroll
            for (int nip = 0; nip < 8; nip++) {
                uint32_t r0, r1, r2, r3;
                uint32_t va = vb0 + ((uint32_t)((nip * 2 + lh) ^ e7) << 4);
                LDSM4T(r0, r1, r2, r3, va);
                uint32_t bf0[2] = { r0, r1 };
                uint32_t bf1[2] = { r2, r3 };
                mma_f16(oacc[2 * nip],     af, bf0);
                mma_f16(oacc[2 * nip + 1], af, bf1);
            }
        }
    }

    // ---- epilogue: fp16 output, l from lacc ----
    const float inv0 = __fdividef(1.f, lacc[0]);
    const float inv1 = __fdividef(1.f, lacc[2]);
    uint32_t* o0 = out16 + (size_t)qr0 * 1024 + h * 64 + t;
    uint32_t* o1 = out16 + (size_t)(qr0 + 8) * 1024 + h * 64 + t;
#pragma unroll
    for (int ni = 0; ni < 16; ni++) {
        o0[ni * 4] = pk(oacc[ni][0] * inv0, oacc[ni][1] * inv0);
        o1[ni * 4] = pk(oacc[ni][2] * inv1, oacc[ni][3] * inv1);
    }
}

// ---------------------------------------------------------------------------
// Inputs (metadata order): hidden_states, cos, sin, attention_mask, wq, wk, wv, wo
// ---------------------------------------------------------------------------
extern "C" void kernel_launch(void* const* d_in, const int* in_sizes, int n_in,
                              void* d_out, int out_size)
{
    const float* hs   = (const float*)d_in[0];
    const float* cosp = (const float*)d_in[1];
    const float* sinp = (const float*)d_in[2];
    const float* wq   = (const float*)d_in[4];
    const float* wk   = (const float*)d_in[5];
    const float* wv   = (const float*)d_in[6];
    const float* wo   = (const float*)d_in[7];
    float* out = (float*)d_out;

    float* qkv = nullptr; uint32_t* qk16 = nullptr; uint32_t* v16 = nullptr;
    uint32_t* hs16 = nullptr; uint32_t* w16 = nullptr;
    uint32_t* wo16 = nullptr; uint32_t* attn16 = nullptr;
    cudaGetSymbolAddress((void**)&qkv,    g_qkv);
    cudaGetSymbolAddress((void**)&qk16,   g_qk16);
    cudaGetSymbolAddress((void**)&v16,    g_v16);
    cudaGetSymbolAddress((void**)&hs16,   g_hs16);
    cudaGetSymbolAddress((void**)&w16,    g_w16);
    cudaGetSymbolAddress((void**)&wo16,   g_wo16);
    cudaGetSymbolAddress((void**)&attn16, g_attn16);

    cudaFuncSetAttribute(gemm_h, cudaFuncAttributeMaxDynamicSharedMemorySize, GEMM_SMEM);
    cudaFuncSetAttribute(attn_mma, cudaFuncAttributeMaxDynamicSharedMemorySize, ATTN_SMEM);

    dim3 blk(256);
    cvt_all<<<(N_CVT + 255) / 256, blk>>>(hs, wq, wk, wv, wo, hs16, w16, wo16);
    gemm_h<<<dim3(3072 / 128, S_LEN / 128), blk, GEMM_SMEM>>>(
        (const __half*)hs16, (const __half*)w16, qkv, HID, QKV_LD);
    rope_pack<<<S_LEN, 256>>>(qkv, qk16, v16, cosp, sinp);
    attn_mma<<<dim3(S_LEN / 128, NH), blk, ATTN_SMEM>>>(qk16, v16, attn16);
    gemm_h<<<dim3(2048 / 128, S_LEN / 128), blk, GEMM_SMEM>>>(
        (const __half*)attn16, (const __half*)wo16, out, HID, HID);
}

// round 15
// speedup vs baseline: 1.6209x; 1.0453x over previous
#include <cuda_runtime.h>
#include <cuda_bf16.h>
#include <cuda_fp16.h>
#include <cstdint>

#define S_LEN   4096
#define HID     2048
#define NH      16
#define NKV     4
#define DH      128
#define QKV_LD  3072
#define QK16_LD 1280
#define Q_SCALE 0.08838834764831845f
#define CAP     50.0f
// exact log2-domain softcap constants (fallback path)
#define SC_IN   0.057707801635558534f   // (2/50)*log2(e)
#define SC_C1   72.13475204444817f      // 50*log2(e)
#define SC_C2   144.26950408889634f     // 100*log2(e)
// polynomial softcap (log2 output): v = s*(PL - s^2*(P3 - P5*s^2))
#define PL  1.4426950408889634f         // log2(e)
#define P3  1.9235933878519513e-4f      // log2(e)/7500
#define P5  3.0777494205631223e-8f      // 2*log2(e)/93750000
#define POLY_LIM 15.0f

// Scratch (device globals: no cudaMalloc allowed)
__device__ float    g_qkv[(size_t)S_LEN * QKV_LD];
__device__ uint32_t g_qk16[(size_t)S_LEN * QK16_LD];
__device__ uint32_t g_v16[(size_t)S_LEN * 256];
__device__ uint32_t g_hs16[(size_t)S_LEN * 1024];
__device__ uint32_t g_w16[(size_t)3072 * 1024];
__device__ uint32_t g_wo16[(size_t)2048 * 1024];
__device__ uint32_t g_attn16[(size_t)S_LEN * 1024];

// ===========================================================================
// Helpers
// ===========================================================================
__device__ __forceinline__ uint32_t pk(float lo, float hi) {
    uint32_t d;
    asm("cvt.rn.f16x2.f32 %0, %1, %2;" : "=r"(d) : "f"(hi), "f"(lo));
    return d;
}
__device__ __forceinline__ float ex2f(float x) {
    float r;
    asm("ex2.approx.f32 %0, %1;" : "=f"(r) : "f"(x));
    return r;
}
__device__ __forceinline__ float rcpf(float x) {
    float r;
    asm("rcp.approx.f32 %0, %1;" : "=f"(r) : "f"(x));
    return r;
}
__device__ __forceinline__ void mma_f16(float* c, const uint32_t* a, const uint32_t* b) {
    asm volatile(
        "mma.sync.aligned.m16n8k16.row.col.f32.f16.f16.f32 "
        "{%0,%1,%2,%3}, {%4,%5,%6,%7}, {%8,%9}, {%0,%1,%2,%3};"
        : "+f"(c[0]), "+f"(c[1]), "+f"(c[2]), "+f"(c[3])
        : "r"(a[0]), "r"(a[1]), "r"(a[2]), "r"(a[3]), "r"(b[0]), "r"(b[1]));
}
__device__ __forceinline__ uint32_t smem_u32(const void* p) {
    uint32_t a;
    asm("{ .reg .u64 t; cvta.to.shared.u64 t, %1; cvt.u32.u64 %0, t; }"
        : "=r"(a) : "l"(p));
    return a;
}
#define LDSM4(r0, r1, r2, r3, addr) \
    asm volatile("ldmatrix.sync.aligned.m8n8.x4.shared.b16 {%0,%1,%2,%3}, [%4];" \
        : "=r"(r0), "=r"(r1), "=r"(r2), "=r"(r3) : "r"(addr))
#define LDSM4T(r0, r1, r2, r3, addr) \
    asm volatile("ldmatrix.sync.aligned.m8n8.x4.trans.shared.b16 {%0,%1,%2,%3}, [%4];" \
        : "=r"(r0), "=r"(r1), "=r"(r2), "=r"(r3) : "r"(addr))
#define CP_A16(saddr, gptr) \
    asm volatile("cp.async.cg.shared.global [%0], [%1], 16;" :: "r"(saddr), "l"(gptr))
#define CP_COMMIT() asm volatile("cp.async.commit_group;" ::: "memory")
#define CP_WAIT(n)  asm volatile("cp.async.wait_group %0;" :: "n"(n) : "memory")

// ---------------------------------------------------------------------------
// Fused f32 -> fp16x2 convert (one launch)
// ---------------------------------------------------------------------------
#define N_HS 2097152
#define N_WQ 1048576
#define N_WK 262144
#define N_WV 262144
#define N_WO 1048576
#define N_CVT (N_HS + N_WQ + N_WK + N_WV + N_WO)

__global__ void cvt_all(const float* __restrict__ hs, const float* __restrict__ wq,
                        const float* __restrict__ wk, const float* __restrict__ wv,
                        const float* __restrict__ wo,
                        uint32_t* __restrict__ hs16, uint32_t* __restrict__ w16,
                        uint32_t* __restrict__ wo16)
{
    int i = blockIdx.x * 256 + threadIdx.x;
    if (i >= N_CVT) return;
    const float* src; uint32_t* dst; int j = i;
    if (j < N_HS)                 { src = hs; dst = hs16; }
    else if ((j -= N_HS) < N_WQ)  { src = wq; dst = w16; }
    else if ((j -= N_WQ) < N_WK)  { src = wk; dst = w16 + (size_t)2048 * 1024; }
    else if ((j -= N_WK) < N_WV)  { src = wv; dst = w16 + (size_t)2560 * 1024; }
    else { j -= N_WV;               src = wo; dst = wo16; }
    float4 v = ((const float4*)src)[j];
    ((uint2*)dst)[j] = make_uint2(pk(v.x, v.y), pk(v.z, v.w));
}

// ===========================================================================
// FP16 GEMM (unchanged — protected)
// ===========================================================================
#define KC 64
#define STAGES 3
#define AST 16384
#define BST 16384
#define STG (AST + BST)
#define GEMM_SMEM (STAGES * STG)

__global__ __launch_bounds__(256, 2) void gemm_h(
    const __half* __restrict__ A, const __half* __restrict__ B,
    float* __restrict__ C, int Kd, int ldc)
{
    extern __shared__ __align__(128) char smc[];
    const uint32_t sb = smem_u32(smc);

    const int tid  = threadIdx.x;
    const int lane = tid & 31;
    const int warp = tid >> 5;
    const int wm   = warp >> 1;
    const int wn   = warp & 1;
    const int bm   = blockIdx.y * 128;
    const int bnG  = blockIdx.x * 128;
    const int NC   = Kd / KC;

    const int lrow = tid >> 3;
    const int lc16 = tid & 7;
    const __half* Ag = A + (size_t)(bm + lrow) * Kd + lc16 * 8;
    const __half* Bg = B + (size_t)(bnG + lrow) * Kd + lc16 * 8;

    uint32_t so[4];
#pragma unroll
    for (int it = 0; it < 4; it++) {
        int row = lrow + it * 32;
        so[it] = (uint32_t)(row * 128 + ((lc16 ^ (row & 7)) << 4));
    }

    const int l15 = lane & 15;
    const int lh  = lane >> 4;
    int aRow[2], bRow[4];
#pragma unroll
    for (int mi = 0; mi < 2; mi++) aRow[mi] = wm * 32 + mi * 16 + l15;
#pragma unroll
    for (int nt = 0; nt < 4; nt++) bRow[nt] = wn * 64 + nt * 16 + l15;

    float acc[2][8][4];
#pragma unroll
    for (int i = 0; i < 2; i++)
#pragma unroll
        for (int j = 0; j < 8; j++)
#pragma unroll
            for (int e = 0; e < 4; e++) acc[i][j][e] = 0.f;

#pragma unroll
    for (int s = 0; s < STAGES - 1; s++) {
        const uint32_t sA = sb + s * STG;
        const uint32_t sB = sA + AST;
        const size_t ko = (size_t)s * KC;
#pragma unroll
        for (int it = 0; it < 4; it++) {
            CP_A16(sA + so[it], Ag + (size_t)(it * 32) * Kd + ko);
            CP_A16(sB + so[it], Bg + (size_t)(it * 32) * Kd + ko);
        }
        CP_COMMIT();
    }

    for (int ic = 0; ic < NC; ic++) {
        if (ic + STAGES - 1 < NC) {
            const int s = (ic + STAGES - 1) % STAGES;
            const uint32_t sA = sb + s * STG;
            const uint32_t sB = sA + AST;
            const size_t ko = (size_t)(ic + STAGES - 1) * KC;
#pragma unroll
            for (int it = 0; it < 4; it++) {
                CP_A16(sA + so[it], Ag + (size_t)(it * 32) * Kd + ko);
                CP_A16(sB + so[it], Bg + (size_t)(it * 32) * Kd + ko);
            }
        }
        CP_COMMIT();
        CP_WAIT(STAGES - 1);
        __syncthreads();

        const uint32_t sA = sb + (ic % STAGES) * STG;
        const uint32_t sB = sA + AST;

#pragma unroll
        for (int ki = 0; ki < 4; ki++) {
            const int kb = ki * 2 + lh;
            uint32_t af[2][4], bv[4][4];
#pragma unroll
            for (int mi = 0; mi < 2; mi++) {
                uint32_t ad = sA + aRow[mi] * 128 + (((kb ^ (aRow[mi] & 7))) << 4);
                LDSM4(af[mi][0], af[mi][1], af[mi][2], af[mi][3], ad);
            }
#pragma unroll
            for (int nt = 0; nt < 4; nt++) {
                uint32_t bd = sB + bRow[nt] * 128 + (((kb ^ (bRow[nt] & 7))) << 4);
                LDSM4(bv[nt][0], bv[nt][1], bv[nt][2], bv[nt][3], bd);
            }
#pragma unroll
            for (int mi = 0; mi < 2; mi++)
#pragma unroll
                for (int j = 0; j < 8; j++) {
                    uint32_t bf[2] = { bv[j >> 1][(j & 1)], bv[j >> 1][2 + (j & 1)] };
                    mma_f16(acc[mi][j], af[mi], bf);
                }
        }
        __syncthreads();
    }

    const int g = lane >> 2, t = lane & 3;
#pragma unroll
    for (int mi = 0; mi < 2; mi++)
#pragma unroll
        for (int j = 0; j < 8; j++) {
            const int row = bm + wm * 32 + mi * 16 + g;
            const int col = bnG + wn * 64 + j * 8 + t * 2;
            float* p0 = C + (size_t)row * ldc + col;
            float* p1 = C + (size_t)(row + 8) * ldc + col;
            *(float2*)p0 = make_float2(acc[mi][j][0], acc[mi][j][1]);
            *(float2*)p1 = make_float2(acc[mi][j][2], acc[mi][j][3]);
        }
}

// ---------------------------------------------------------------------------
// RoPE + Q scale -> g_qk16; V -> g_v16 (unchanged)
// ---------------------------------------------------------------------------
__global__ void rope_pack(const float* __restrict__ qkv,
                          uint32_t* __restrict__ qk16, uint32_t* __restrict__ v16,
                          const float* __restrict__ cosp, const float* __restrict__ sinp)
{
    const int s = blockIdx.x;
    const float* c  = cosp + (size_t)s * DH;
    const float* sn = sinp + (size_t)s * DH;
    const float* row = qkv + (size_t)s * QKV_LD;
    uint32_t* orow = qk16 + (size_t)s * QK16_LD;
    uint32_t* vrow = v16 + (size_t)s * 256;
    for (int i = threadIdx.x; i < 24 * 32; i += blockDim.x) {
        int hh = i >> 5;
        int c0 = i & 31;
        if (hh < 20) {
            int d0 = 2 * c0;
            int base = (hh < 16) ? hh * 128 : (2048 + (hh - 16) * 128);
            float x1a = row[base + d0],      x1b = row[base + d0 + 1];
            float x2a = row[base + d0 + 64], x2b = row[base + d0 + 65];
            float y1a = x1a * c[d0]      - x2a * sn[d0];
            float y1b = x1b * c[d0 + 1]  - x2b * sn[d0 + 1];
            float y2a = x2a * c[d0 + 64] + x1a * sn[d0 + 64];
            float y2b = x2b * c[d0 + 65] + x1b * sn[d0 + 65];
            if (hh < 16) { y1a *= Q_SCALE; y1b *= Q_SCALE; y2a *= Q_SCALE; y2b *= Q_SCALE; }
            int obase = (hh < 16) ? hh * 64 : (1024 + (hh - 16) * 64);
            orow[obase + c0]      = pk(y1a, y1b);
            orow[obase + 32 + c0] = pk(y2a, y2b);
        } else {
            int base = 2560 + (hh - 20) * 128;
            int obase = (hh - 20) * 64;
            vrow[obase + c0]      = pk(row[base + 2 * c0],      row[base + 2 * c0 + 1]);
            vrow[obase + 32 + c0] = pk(row[base + 64 + 2 * c0], row[base + 64 + 2 * c0 + 1]);
        }
    }
}

// ===========================================================================
// Flash attention: 4 warps x 32 q-rows (m32 warp tile). K/V fragments shared
// across the 2 m16 slabs -> LDSM per unit work ~halved. 128 thr, 2 CTAs/SM,
// 256 regs/thread available. R14 softmax (poly + vote) retained per slab.
// smem: Q 32K | K0/K1 32K | V0/V1 32K | P 16K = 112 KB
// ===========================================================================
#define ATTN_SMEM 114688
#define SQ_OFF 0
#define SK_OFF 32768
#define SV_OFF 65536
#define SP_OFF 98304

__global__ __launch_bounds__(128, 2) void attn_mma(
    const uint32_t* __restrict__ qk16, const uint32_t* __restrict__ v16,
    uint32_t* __restrict__ out16)
{
    extern __shared__ __align__(128) char sm[];
    const uint32_t sb = smem_u32(sm);
    const uint32_t sQ = sb + SQ_OFF;

    const int tid  = threadIdx.x;
    const int lane = tid & 31;
    const int warp = tid >> 5;          // 0..3
    const int qb   = (int)gridDim.x - 1 - (int)blockIdx.x;
    const int h    = blockIdx.y;
    const int kvg  = h >> 2;

    const int g = lane >> 2, t = lane & 3;
    const int l15 = lane & 15, lh = lane >> 4;
    const int e7 = l15 & 7;

    const char* Qg = (const char*)(qk16 + (size_t)h * 64);
    const char* Kg = (const char*)(qk16 + 1024 + (size_t)kvg * 64);
    const char* Vg = (const char*)(v16 + (size_t)kvg * 64);

    // ---- prologue loads (128 threads) ----
#pragma unroll
    for (int i = 0; i < 16; i++) {
        int idx = tid + i * 128;
        int row = idx >> 4, u = idx & 15;
        CP_A16(sQ + row * 256 + ((u ^ (row & 7)) << 4),
               Qg + (size_t)(qb * 128 + row) * 5120 + u * 16);
    }
#pragma unroll
    for (int i = 0; i < 8; i++) {
        int idx = tid + i * 128;
        int row = idx >> 4, u = idx & 15;
        uint32_t so = row * 256 + ((u ^ (row & 7)) << 4);
        CP_A16(sb + SK_OFF + so, Kg + (size_t)row * 5120 + u * 16);
        CP_A16(sb + SV_OFF + so, Vg + (size_t)row * 1024 + u * 16);
    }
    CP_COMMIT();

    float oacc[2][16][4], lacc[2][4];
#pragma unroll
    for (int s = 0; s < 2; s++) {
#pragma unroll
        for (int i = 0; i < 16; i++)
#pragma unroll
            for (int e = 0; e < 4; e++) oacc[s][i][e] = 0.f;
#pragma unroll
        for (int e = 0; e < 4; e++) lacc[s][e] = 0.f;
    }
    float mLo[2] = { -1e30f, -1e30f }, mHi[2] = { -1e30f, -1e30f };

    const int qrBase = qb * 128 + warp * 32 + g;   // slab s adds s*16
    const int ntiles = 2 * qb + 2;

    // kt-invariant bases
    uint32_t qbs[2], prb[2];
#pragma unroll
    for (int s = 0; s < 2; s++) {
        qbs[s] = sQ + (uint32_t)((warp * 32 + s * 16 + l15) * 256);
        prb[s] = sb + SP_OFF + warp * 4096 + s * 2048 + l15 * 128;
    }
    const uint32_t kofsL = (uint32_t)(l15 * 256);
    const uint32_t ones2[2] = { 0x3C003C00u, 0x3C003C00u };

    // P store addresses: [slab][nt]
    uint32_t pst[2][8];
#pragma unroll
    for (int s = 0; s < 2; s++)
#pragma unroll
        for (int nt = 0; nt < 8; nt++)
            pst[s][nt] = (uint32_t)(SP_OFF + warp * 4096 + s * 2048 +
                                    g * 128 + ((nt ^ g) << 4) + t * 4);

    for (int kt = 0; kt < ntiles; kt++) {
        CP_WAIT(0);
        __syncthreads();

        if (kt + 1 < ntiles) {
            const uint32_t dK = sb + SK_OFF + ((kt + 1) & 1) * 16384;
            const uint32_t dV = sb + SV_OFF + ((kt + 1) & 1) * 16384;
#pragma unroll
            for (int i = 0; i < 8; i++) {
                int idx = tid + i * 128;
                int row = idx >> 4, u = idx & 15;
                uint32_t so = row * 256 + ((u ^ (row & 7)) << 4);
                CP_A16(dK + so, Kg + (size_t)((kt + 1) * 64 + row) * 5120 + u * 16);
                CP_A16(dV + so, Vg + (size_t)((kt + 1) * 64 + row) * 1024 + u * 16);
            }
            CP_COMMIT();
        }

        const uint32_t cK = sb + SK_OFF + (kt & 1) * 16384;
        const uint32_t cV = sb + SV_OFF + (kt & 1) * 16384;

        // ---- QK: both slabs share K fragments ----
        float acc[2][8][4];
#pragma unroll
        for (int s = 0; s < 2; s++)
#pragma unroll
            for (int nt = 0; nt < 8; nt++)
#pragma unroll
                for (int e = 0; e < 4; e++) acc[s][nt][e] = 0.f;

#pragma unroll
        for (int ki = 0; ki < 8; ki++) {
            const uint32_t xo = (uint32_t)(((ki * 2 + lh) ^ e7) << 4);
            uint32_t afA[4], afB[4];
            LDSM4(afA[0], afA[1], afA[2], afA[3], qbs[0] + xo);
            LDSM4(afB[0], afB[1], afB[2], afB[3], qbs[1] + xo);
            const uint32_t kb0 = cK + kofsL + xo;
#pragma unroll
            for (int ntp = 0; ntp < 4; ntp++) {
                uint32_t r0, r1, r2, r3;
                LDSM4(r0, r1, r2, r3, kb0 + ntp * 4096);
                uint32_t bf0[2] = { r0, r2 };
                uint32_t bf1[2] = { r1, r3 };
                mma_f16(acc[0][2 * ntp],     afA, bf0);
                mma_f16(acc[0][2 * ntp + 1], afA, bf1);
                mma_f16(acc[1][2 * ntp],     afB, bf0);
                mma_f16(acc[1][2 * ntp + 1], afB, bf1);
            }
        }

        // ---- softcap vote (both slabs) ----
        float ma = 0.f;
#pragma unroll
        for (int s = 0; s < 2; s++)
#pragma unroll
            for (int nt = 0; nt < 8; nt++)
#pragma unroll
                for (int e = 0; e < 4; e++) ma = fmaxf(ma, fabsf(acc[s][nt][e]));
        const bool poly = __all_sync(0xffffffffu, ma < POLY_LIM);
        const bool diag = (kt >= 2 * qb);

#pragma unroll
        for (int s = 0; s < 2; s++) {
            const int qrA = qrBase + s * 16, qrB = qrA + 8;
            float mt0 = -1e30f, mt1 = -1e30f;
            if (poly) {
#pragma unroll
                for (int nt = 0; nt < 8; nt++) {
#pragma unroll
                    for (int e = 0; e < 4; e++) {
                        float sc = acc[s][nt][e];
                        float s2 = sc * sc;
                        float tt = fmaf(-P5, s2, P3);
                        float v  = sc * fmaf(-s2, tt, PL);
                        if (diag) {
                            int kc = kt * 64 + nt * 8 + 2 * t + (e & 1);
                            if (kc > ((e >> 1) ? qrB : qrA)) v = -1e30f;
                        }
                        acc[s][nt][e] = v;
                        if (e < 2) mt0 = fmaxf(mt0, v); else mt1 = fmaxf(mt1, v);
                    }
                }
            } else {
#pragma unroll
                for (int nt = 0; nt < 8; nt++) {
#pragma unroll
                    for (int e = 0; e < 4; e++) {
                        float w = ex2f(acc[s][nt][e] * SC_IN);
                        float v = fmaf(-SC_C2, rcpf(w + 1.f), SC_C1);
                        if (diag) {
                            int kc = kt * 64 + nt * 8 + 2 * t + (e & 1);
                            if (kc > ((e >> 1) ? qrB : qrA)) v = -1e30f;
                        }
                        acc[s][nt][e] = v;
                        if (e < 2) mt0 = fmaxf(mt0, v); else mt1 = fmaxf(mt1, v);
                    }
                }
            }

            // vote-gated max reduction + rescale (per slab)
            const bool need = (mt0 > mLo[s]) || (mt1 > mHi[s]);
            if (__any_sync(0xffffffffu, need)) {
                mt0 = fmaxf(mt0, __shfl_xor_sync(0xffffffffu, mt0, 1));
                mt0 = fmaxf(mt0, __shfl_xor_sync(0xffffffffu, mt0, 2));
                mt1 = fmaxf(mt1, __shfl_xor_sync(0xffffffffu, mt1, 1));
                mt1 = fmaxf(mt1, __shfl_xor_sync(0xffffffffu, mt1, 2));
                const float mn0 = fmaxf(mLo[s], mt0), mn1 = fmaxf(mHi[s], mt1);
                const float al0 = ex2f(mLo[s] - mn0), al1 = ex2f(mHi[s] - mn1);
                mLo[s] = mn0; mHi[s] = mn1;
#pragma unroll
                for (int ni = 0; ni < 16; ni++) {
                    oacc[s][ni][0] *= al0; oacc[s][ni][1] *= al0;
                    oacc[s][ni][2] *= al1; oacc[s][ni][3] *= al1;
                }
                lacc[s][0] *= al0; lacc[s][1] *= al0;
                lacc[s][2] *= al1; lacc[s][3] *= al1;
            }

            // p = ex2(v - m), pack, store to P smem
#pragma unroll
            for (int nt = 0; nt < 8; nt++) {
                float p0 = ex2f(acc[s][nt][0] - mLo[s]);
                float p1 = ex2f(acc[s][nt][1] - mLo[s]);
                float p2 = ex2f(acc[s][nt][2] - mHi[s]);
                float p3 = ex2f(acc[s][nt][3] - mHi[s]);
                *(uint32_t*)(sm + pst[s][nt])           = pk(p0, p1);
                *(uint32_t*)(sm + pst[s][nt] + 8 * 128) = pk(p2, p3);
            }
        }
        __syncwarp();

        // ---- PV: V fragments shared across slabs ----
#pragma unroll
        for (int ki = 0; ki < 4; ki++) {
            const uint32_t xo = (uint32_t)(((ki * 2 + lh) ^ e7) << 4);
            uint32_t afP0[4], afP1[4];
            LDSM4(afP0[0], afP0[1], afP0[2], afP0[3], prb[0] + xo);
            LDSM4(afP1[0], afP1[1], afP1[2], afP1[3], prb[1] + xo);
            mma_f16(lacc[0], afP0, ones2);
            mma_f16(lacc[1], afP1, ones2);
            const uint32_t vb0 = cV + ki * 4096 + kofsL;
#pragma unroll
            for (int nip = 0; nip < 8; nip++) {
                uint32_t r0, r1, r2, r3;
                uint32_t va = vb0 + ((uint32_t)((nip * 2 + lh) ^ e7) << 4);
                LDSM4T(r0, r1, r2, r3, va);
                uint32_t bf0[2] = { r0, r1 };
                uint32_t bf1[2] = { r2, r3 };
                mma_f16(oacc[0][2 * nip],     afP0, bf0);
                mma_f16(oacc[0][2 * nip + 1], afP0, bf1);
                mma_f16(oacc[1][2 * nip],     afP1, bf0);
                mma_f16(oacc[1][2 * nip + 1], afP1, bf1);
            }
        }
    }

    // ---- epilogue: fp16 output ----
#pragma unroll
    for (int s = 0; s < 2; s++) {
        const float inv0 = __fdividef(1.f, lacc[s][0]);
        const float inv1 = __fdividef(1.f, lacc[s][2]);
        const int qr = qrBase + s * 16;
        uint32_t* o0 = out16 + (size_t)qr * 1024 + h * 64 + t;
        uint32_t* o1 = out16 + (size_t)(qr + 8) * 1024 + h * 64 + t;
#pragma unroll
        for (int ni = 0; ni < 16; ni++) {
            o0[ni * 4] = pk(oacc[s][ni][0] * inv0, oacc[s][ni][1] * inv0);
            o1[ni * 4] = pk(oacc[s][ni][2] * inv1, oacc[s][ni][3] * inv1);
        }
    }
}

// ---------------------------------------------------------------------------
// Inputs (metadata order): hidden_states, cos, sin, attention_mask, wq, wk, wv, wo
// ---------------------------------------------------------------------------
extern "C" void kernel_launch(void* const* d_in, const int* in_sizes, int n_in,
                              void* d_out, int out_size)
{
    const float* hs   = (const float*)d_in[0];
    const float* cosp = (const float*)d_in[1];
    const float* sinp = (const float*)d_in[2];
    const float* wq   = (const float*)d_in[4];
    const float* wk   = (const float*)d_in[5];
    const float* wv   = (const float*)d_in[6];
    const float* wo   = (const float*)d_in[7];
    float* out = (float*)d_out;

    float* qkv = nullptr; uint32_t* qk16 = nullptr; uint32_t* v16 = nullptr;
    uint32_t* hs16 = nullptr; uint32_t* w16 = nullptr;
    uint32_t* wo16 = nullptr; uint32_t* attn16 = nullptr;
    cudaGetSymbolAddress((void**)&qkv,    g_qkv);
    cudaGetSymbolAddress((void**)&qk16,   g_qk16);
    cudaGetSymbolAddress((void**)&v16,    g_v16);
    cudaGetSymbolAddress((void**)&hs16,   g_hs16);
    cudaGetSymbolAddress((void**)&w16,    g_w16);
    cudaGetSymbolAddress((void**)&wo16,   g_wo16);
    cudaGetSymbolAddress((void**)&attn16, g_attn16);

    cudaFuncSetAttribute(gemm_h, cudaFuncAttributeMaxDynamicSharedMemorySize, GEMM_SMEM);
    cudaFuncSetAttribute(attn_mma, cudaFuncAttributeMaxDynamicSharedMemorySize, ATTN_SMEM);

    dim3 blk(256);
    cvt_all<<<(N_CVT + 255) / 256, blk>>>(hs, wq, wk, wv, wo, hs16, w16, wo16);
    gemm_h<<<dim3(3072 / 128, S_LEN / 128), blk, GEMM_SMEM>>>(
        (const __half*)hs16, (const __half*)w16, qkv, HID, QKV_LD);
    rope_pack<<<S_LEN, 256>>>(qkv, qk16, v16, cosp, sinp);
    attn_mma<<<dim3(S_LEN / 128, NH), dim3(128), ATTN_SMEM>>>(qk16, v16, attn16);
    gemm_h<<<dim3(2048 / 128, S_LEN / 128), blk, GEMM_SMEM>>>(
        (const __half*)attn16, (const __half*)wo16, out, HID, HID);
}